// round 1
// baseline (speedup 1.0000x reference)
#include <cuda_runtime.h>
#include <cuda_bf16.h>
#include <math.h>

// Problem constants
#define BB   2
#define TT   2048
#define MROWS (BB*TT)        // 4096
#define DIM  1024
#define HID  4096
#define NH   16
#define KVH  4
#define HD   64
#define WIN  512

// ---------------- scratch (device globals; no allocs allowed) ----------------
__device__ float g_xn[MROWS * DIM];       // rmsnorm(x) / reused as hn
__device__ float g_q [MROWS * NH * HD];   // 4096 x 1024
__device__ float g_k [MROWS * KVH * HD];  // 4096 x 256
__device__ float g_v [MROWS * KVH * HD];
__device__ float g_y [MROWS * NH * HD];   // attention output
__device__ float g_h [MROWS * DIM];       // residual 1
__device__ float g_u [MROWS * HID];       // w1 out, then silu(u)*g in place

// ---------------- row RMSNorm over DIM=1024 ----------------
__global__ void rmsnorm_kernel(const float* __restrict__ x,
                               const float* __restrict__ w,
                               float* __restrict__ out, float eps) {
    int row = blockIdx.x;
    int tid = threadIdx.x;                    // 256 threads, 4 floats each
    const float4* xr = reinterpret_cast<const float4*>(x + (size_t)row * DIM);
    float4 v = xr[tid];
    float ss = v.x*v.x + v.y*v.y + v.z*v.z + v.w*v.w;
    // block reduce
    #pragma unroll
    for (int o = 16; o; o >>= 1) ss += __shfl_xor_sync(0xffffffffu, ss, o);
    __shared__ float red[8];
    __shared__ float stot;
    int lane = tid & 31, wid = tid >> 5;
    if (lane == 0) red[wid] = ss;
    __syncthreads();
    if (tid == 0) {
        float s = 0.f;
        #pragma unroll
        for (int i = 0; i < 8; i++) s += red[i];
        stot = rsqrtf(s * (1.0f / DIM) + eps);
    }
    __syncthreads();
    float sc = stot;
    const float4* wr = reinterpret_cast<const float4*>(w);
    float4 wv = wr[tid];
    float4 o4 = make_float4(v.x*sc*wv.x, v.y*sc*wv.y, v.z*sc*wv.z, v.w*sc*wv.w);
    reinterpret_cast<float4*>(out + (size_t)row * DIM)[tid] = o4;
}

// ---------------- per-head RMSNorm over HD=64 (in place) ----------------
__global__ void headnorm_kernel(float* __restrict__ q, const float* __restrict__ w) {
    int warp = threadIdx.x >> 5;
    int lane = threadIdx.x & 31;
    size_t r = (size_t)blockIdx.x * 4 + warp;     // one head-row per warp
    float2* p = reinterpret_cast<float2*>(q + r * HD) + lane;
    float2 v = *p;
    float ss = v.x*v.x + v.y*v.y;
    #pragma unroll
    for (int o = 16; o; o >>= 1) ss += __shfl_xor_sync(0xffffffffu, ss, o);
    float sc = rsqrtf(ss * (1.0f / HD) + 1e-6f);
    float2 wv = reinterpret_cast<const float2*>(w)[lane];
    *p = make_float2(v.x*sc*wv.x, v.y*sc*wv.y);
}

// ---------------- GEMM: C[M,N] = A[M,K] @ W[N,K]^T ----------------
// BM=BN=128, BK=16, 256 threads, 8x8 per thread. All dims divide tiles.
// EPI: 0 none; 1 C = res + acc*scale[col]; 2 C = silu(upre)*acc
template<int EPI>
__global__ void __launch_bounds__(256)
gemm_kernel(const float* __restrict__ A, const float* __restrict__ W,
            float* __restrict__ C, int M, int N, int K,
            const float* __restrict__ res, const float* __restrict__ scale,
            const float* __restrict__ upre) {
    __shared__ float As[16][128];
    __shared__ float Bs[16][128];
    const int tid = threadIdx.x;
    const int tx = tid & 15, ty = tid >> 4;
    const int brow0 = blockIdx.y * 128;
    const int bcol0 = blockIdx.x * 128;

    float acc[8][8];
    #pragma unroll
    for (int i = 0; i < 8; i++)
        #pragma unroll
        for (int j = 0; j < 8; j++) acc[i][j] = 0.f;

    const int lr = tid >> 2;          // 0..63
    const int lk = (tid & 3) * 4;     // 0,4,8,12
    const float* Ap  = A + (size_t)(brow0 + lr) * K + lk;
    const float* Ap2 = Ap + (size_t)64 * K;
    const float* Wp  = W + (size_t)(bcol0 + lr) * K + lk;
    const float* Wp2 = Wp + (size_t)64 * K;

    for (int k0 = 0; k0 < K; k0 += 16) {
        float4 a0 = *reinterpret_cast<const float4*>(Ap  + k0);
        float4 a1 = *reinterpret_cast<const float4*>(Ap2 + k0);
        float4 w0 = *reinterpret_cast<const float4*>(Wp  + k0);
        float4 w1 = *reinterpret_cast<const float4*>(Wp2 + k0);
        __syncthreads();   // protect previous tile's reads
        As[lk+0][lr] = a0.x; As[lk+1][lr] = a0.y; As[lk+2][lr] = a0.z; As[lk+3][lr] = a0.w;
        As[lk+0][lr+64] = a1.x; As[lk+1][lr+64] = a1.y; As[lk+2][lr+64] = a1.z; As[lk+3][lr+64] = a1.w;
        Bs[lk+0][lr] = w0.x; Bs[lk+1][lr] = w0.y; Bs[lk+2][lr] = w0.z; Bs[lk+3][lr] = w0.w;
        Bs[lk+0][lr+64] = w1.x; Bs[lk+1][lr+64] = w1.y; Bs[lk+2][lr+64] = w1.z; Bs[lk+3][lr+64] = w1.w;
        __syncthreads();
        #pragma unroll
        for (int kk = 0; kk < 16; kk++) {
            float a[8], b[8];
            *reinterpret_cast<float4*>(a)     = *reinterpret_cast<const float4*>(&As[kk][ty*8]);
            *reinterpret_cast<float4*>(a + 4) = *reinterpret_cast<const float4*>(&As[kk][ty*8+4]);
            *reinterpret_cast<float4*>(b)     = *reinterpret_cast<const float4*>(&Bs[kk][tx*8]);
            *reinterpret_cast<float4*>(b + 4) = *reinterpret_cast<const float4*>(&Bs[kk][tx*8+4]);
            #pragma unroll
            for (int i = 0; i < 8; i++)
                #pragma unroll
                for (int j = 0; j < 8; j++)
                    acc[i][j] += a[i] * b[j];
        }
    }

    #pragma unroll
    for (int i = 0; i < 8; i++) {
        int row = brow0 + ty*8 + i;
        size_t base = (size_t)row * N + bcol0 + tx*8;
        if (EPI == 0) {
            #pragma unroll
            for (int j = 0; j < 8; j += 4) {
                float4 o = make_float4(acc[i][j], acc[i][j+1], acc[i][j+2], acc[i][j+3]);
                *reinterpret_cast<float4*>(C + base + j) = o;
            }
        } else if (EPI == 1) {
            #pragma unroll
            for (int j = 0; j < 8; j++) {
                int col = bcol0 + tx*8 + j;
                C[base + j] = res[base + j] + acc[i][j] * scale[col];
            }
        } else {  // EPI == 2 : silu(u) * acc
            #pragma unroll
            for (int j = 0; j < 8; j++) {
                float uv = upre[base + j];
                float s  = uv / (1.0f + __expf(-uv));
                C[base + j] = s * acc[i][j];
            }
        }
    }
}

// ---------------- sliding-window GQA attention ----------------
// grid (T/64, H, B), 64 threads; one query per thread; K/V tiles in shared.
__global__ void __launch_bounds__(64)
attn_kernel(const float* __restrict__ q, const float* __restrict__ k,
            const float* __restrict__ v, float* __restrict__ y) {
    __shared__ float Ksm[64 * HD];
    __shared__ float Vsm[64 * HD];
    float4* Ks4 = reinterpret_cast<float4*>(Ksm);
    float4* Vs4 = reinterpret_cast<float4*>(Vsm);

    const int m   = blockIdx.x;      // q tile
    const int h   = blockIdx.y;
    const int b   = blockIdx.z;
    const int tid = threadIdx.x;
    const int qi  = m * 64 + tid;
    const int kvh = h >> 2;          // H/KVH = 4

    // load query row into registers
    float4 qv[16];
    const float4* qp = reinterpret_cast<const float4*>(
        q + ((size_t)(b * TT + qi) * (NH * HD) + h * HD));
    #pragma unroll
    for (int d = 0; d < 16; d++) qv[d] = qp[d];

    float4 acc4[16];
    #pragma unroll
    for (int d = 0; d < 16; d++) acc4[d] = make_float4(0.f, 0.f, 0.f, 0.f);
    float mx = -INFINITY, l = 0.f;

    int t0 = (m >= 8) ? (m - 8) * 64 : 0;
    for (int tile = t0; tile <= m * 64; tile += 64) {
        // cooperative load of K/V 64x64 tiles (coalesced, conflict-free)
        const float4* kb = reinterpret_cast<const float4*>(
            k + ((size_t)(b * TT + tile) * (KVH * HD) + kvh * HD));
        const float4* vb = reinterpret_cast<const float4*>(
            v + ((size_t)(b * TT + tile) * (KVH * HD) + kvh * HD));
        const int rstride = (KVH * HD) / 4;   // 64 float4 per source row
        #pragma unroll
        for (int i = 0; i < 16; i++) {
            int idx = i * 64 + tid;
            int r = idx >> 4, c = idx & 15;
            Ks4[idx] = kb[r * rstride + c];
            Vs4[idx] = vb[r * rstride + c];
        }
        __syncthreads();

        int jmax = qi - tile; if (jmax > 63) jmax = 63;
        int jmin = (qi - (WIN - 1)) - tile; if (jmin < 0) jmin = 0;
        for (int j = jmin; j <= jmax; j++) {
            const float4* kr = Ks4 + j * 16;
            float s = 0.f;
            #pragma unroll
            for (int d = 0; d < 16; d++) {
                float4 kk = kr[d];
                s += qv[d].x*kk.x + qv[d].y*kk.y + qv[d].z*kk.z + qv[d].w*kk.w;
            }
            s *= 0.125f;  // 1/sqrt(64)
            if (s > mx) {
                float corr = __expf(mx - s);   // 0 on first key (exp(-inf))
                mx = s;
                l *= corr;
                #pragma unroll
                for (int d = 0; d < 16; d++) {
                    acc4[d].x *= corr; acc4[d].y *= corr;
                    acc4[d].z *= corr; acc4[d].w *= corr;
                }
            }
            float p = __expf(s - mx);
            l += p;
            const float4* vr = Vs4 + j * 16;
            #pragma unroll
            for (int d = 0; d < 16; d++) {
                float4 vv = vr[d];
                acc4[d].x += p * vv.x; acc4[d].y += p * vv.y;
                acc4[d].z += p * vv.z; acc4[d].w += p * vv.w;
            }
        }
        __syncthreads();
    }

    float inv = 1.0f / l;
    float4* yp = reinterpret_cast<float4*>(
        y + ((size_t)(b * TT + qi) * (NH * HD) + h * HD));
    #pragma unroll
    for (int d = 0; d < 16; d++) {
        yp[d] = make_float4(acc4[d].x*inv, acc4[d].y*inv, acc4[d].z*inv, acc4[d].w*inv);
    }
}

// ---------------- launch ----------------
extern "C" void kernel_launch(void* const* d_in, const int* in_sizes, int n_in,
                              void* d_out, int out_size) {
    const float* x          = (const float*)d_in[0];
    const float* wq         = (const float*)d_in[1];
    const float* wk         = (const float*)d_in[2];
    const float* wv         = (const float*)d_in[3];
    const float* wo         = (const float*)d_in[4];
    const float* w1         = (const float*)d_in[5];
    const float* w2         = (const float*)d_in[6];
    const float* w3         = (const float*)d_in[7];
    const float* q_norm_w   = (const float*)d_in[8];
    const float* k_norm_w   = (const float*)d_in[9];
    const float* attn_norm_w= (const float*)d_in[10];
    const float* ffn_norm_w = (const float*)d_in[11];
    const float* attn_scale = (const float*)d_in[12];
    const float* ffn_scale  = (const float*)d_in[13];
    float* out = (float*)d_out;

    float *xn, *q, *k, *v, *y, *h, *u;
    cudaGetSymbolAddress((void**)&xn, g_xn);
    cudaGetSymbolAddress((void**)&q,  g_q);
    cudaGetSymbolAddress((void**)&k,  g_k);
    cudaGetSymbolAddress((void**)&v,  g_v);
    cudaGetSymbolAddress((void**)&y,  g_y);
    cudaGetSymbolAddress((void**)&h,  g_h);
    cudaGetSymbolAddress((void**)&u,  g_u);

    const int M = MROWS;

    // 1. xn = rmsnorm(x, attn_norm_w)
    rmsnorm_kernel<<<M, 256>>>(x, attn_norm_w, xn, 1e-5f);

    // 2. q/k/v projections
    gemm_kernel<0><<<dim3(DIM/128, M/128), 256>>>(xn, wq, q, M, DIM, DIM, nullptr, nullptr, nullptr);
    gemm_kernel<0><<<dim3((KVH*HD)/128, M/128), 256>>>(xn, wk, k, M, KVH*HD, DIM, nullptr, nullptr, nullptr);
    gemm_kernel<0><<<dim3((KVH*HD)/128, M/128), 256>>>(xn, wv, v, M, KVH*HD, DIM, nullptr, nullptr, nullptr);

    // 3. per-head q/k rmsnorm
    headnorm_kernel<<<(M * NH) / 4, 128>>>(q, q_norm_w);
    headnorm_kernel<<<(M * KVH) / 4, 128>>>(k, k_norm_w);

    // 4. sliding-window attention
    attn_kernel<<<dim3(TT/64, NH, BB), 64>>>(q, k, v, y);

    // 5. h = x + (y @ wo.T) * attn_scale
    gemm_kernel<1><<<dim3(DIM/128, M/128), 256>>>(y, wo, h, M, DIM, DIM, x, attn_scale, nullptr);

    // 6. hn = rmsnorm(h, ffn_norm_w)  (reuse xn)
    rmsnorm_kernel<<<M, 256>>>(h, ffn_norm_w, xn, 1e-5f);

    // 7. u = hn @ w1.T ; u = silu(u) * (hn @ w3.T)
    gemm_kernel<0><<<dim3(HID/128, M/128), 256>>>(xn, w1, u, M, HID, DIM, nullptr, nullptr, nullptr);
    gemm_kernel<2><<<dim3(HID/128, M/128), 256>>>(xn, w3, u, M, HID, DIM, nullptr, nullptr, u);

    // 8. out = h + (u @ w2.T) * ffn_scale
    gemm_kernel<1><<<dim3(DIM/128, M/128), 256>>>(u, w2, out, M, DIM, HID, h, ffn_scale, nullptr);
}

// round 3
// speedup vs baseline: 2.1428x; 2.1428x over previous
#include <cuda_runtime.h>
#include <cuda_bf16.h>
#include <math.h>
#include <stdint.h>

// Problem constants
#define BB   2
#define TT   2048
#define MROWS (BB*TT)        // 4096
#define DIM  1024
#define HID  4096
#define NH   16
#define KVH  4
#define HD   64
#define WIN  512

// ---------------- scratch (device globals; no allocs allowed) ----------------
__device__ float g_xn[MROWS * DIM];
__device__ float g_q [MROWS * NH * HD];
__device__ float g_k [MROWS * KVH * HD];
__device__ float g_v [MROWS * KVH * HD];
__device__ float g_y [MROWS * NH * HD];
__device__ float g_h [MROWS * DIM];
__device__ float g_u [MROWS * HID];

// ================= helpers =================
__device__ __forceinline__ uint32_t smem_u32(const void* p) {
    uint32_t a;
    asm("{ .reg .u64 t; cvta.to.shared.u64 t, %1; cvt.u32.u64 %0, t; }" : "=r"(a) : "l"(p));
    return a;
}
__device__ __forceinline__ void cp_async16(uint32_t dst, const void* src) {
    asm volatile("cp.async.cg.shared.global [%0], [%1], 16;" :: "r"(dst), "l"(src) : "memory");
}
__device__ __forceinline__ void cp_commit() {
    asm volatile("cp.async.commit_group;" ::: "memory");
}
__device__ __forceinline__ void cp_wait2() {
    asm volatile("cp.async.wait_group 2;" ::: "memory");
}
__device__ __forceinline__ void mma_tf32(float* d, const uint32_t* a, const uint32_t* b) {
    asm volatile(
        "mma.sync.aligned.m16n8k8.row.col.f32.tf32.tf32.f32 "
        "{%0,%1,%2,%3}, {%4,%5,%6,%7}, {%8,%9}, {%0,%1,%2,%3};"
        : "+f"(d[0]), "+f"(d[1]), "+f"(d[2]), "+f"(d[3])
        : "r"(a[0]), "r"(a[1]), "r"(a[2]), "r"(a[3]), "r"(b[0]), "r"(b[1]));
}

// ================= tf32 mma.sync GEMM =================
// C[M,N] = A[M,K] @ W[N,K]^T.  BM=128, BN=128, BK=32, 3-stage cp.async.
// 8 warps: wm = wid&1 (64 rows), wn = wid>>1 (32 cols).
// EPI: 0 none; 1 C = res + acc*scale[col]; 2 C = silu(upre)*acc
// If W2 != null: dual mode (blockIdx.x>>1 selects {W,C} vs {W2,C2}; bcol0=(x&1)*128)
#define GBM 128
#define GBN 128
#define GBK 32
#define GSTAGES 3
#define ASTRIDE 36
#define TILE_FLOATS (GBM*ASTRIDE)       // 4608
#define STAGE_FLOATS (2*TILE_FLOATS)    // 9216
#define STAGE_BYTES (STAGE_FLOATS*4)    // 36864
#define GSMEM_BYTES (GSTAGES*STAGE_BYTES)  // 110592

template<int EPI>
__global__ void __launch_bounds__(256, 1)
gemm_mma(const float* __restrict__ A, const float* __restrict__ W,
         float* __restrict__ C, int K, int N,
         const float* __restrict__ res, const float* __restrict__ scale,
         const float* __restrict__ upre,
         const float* __restrict__ W2, float* __restrict__ C2) {
    extern __shared__ float sm[];
    const uint32_t sb = smem_u32(sm);
    const int tid = threadIdx.x;
    const int wid = tid >> 5, lane = tid & 31;
    const int wm = wid & 1, wn = wid >> 1;
    const int lr = lane >> 2, lc = lane & 3;

    const float* Wp = W;
    float* Cp = C;
    int bcol0;
    if (W2 != nullptr) {
        if (blockIdx.x >> 1) { Wp = W2; Cp = C2; }
        bcol0 = (blockIdx.x & 1) * GBN;
    } else {
        bcol0 = blockIdx.x * GBN;
    }
    const int brow0 = blockIdx.y * GBM;

    // loader mapping: 4 float4 per thread per tile
    uint32_t aoff[4], boff[4];
    const float* ag[4];
    const float* bg[4];
    #pragma unroll
    for (int j = 0; j < 4; j++) {
        int f = tid + j * 256;
        int row = f >> 3, kc = (f & 7) * 4;
        aoff[j] = (uint32_t)(row * ASTRIDE + kc) * 4u;
        boff[j] = aoff[j] + TILE_FLOATS * 4u;
        ag[j] = A  + (size_t)(brow0 + row) * K + kc;
        bg[j] = Wp + (size_t)(bcol0 + row) * K + kc;
    }

    const int NC = K / GBK;

    // prologue: fill 3 stages
    #pragma unroll
    for (int s = 0; s < GSTAGES; s++) {
        uint32_t so = sb + s * STAGE_BYTES;
        int k0 = s * GBK;
        #pragma unroll
        for (int j = 0; j < 4; j++) cp_async16(so + aoff[j], ag[j] + k0);
        #pragma unroll
        for (int j = 0; j < 4; j++) cp_async16(so + boff[j], bg[j] + k0);
        cp_commit();
    }

    float acc[4][4][4];
    #pragma unroll
    for (int mt = 0; mt < 4; mt++)
        #pragma unroll
        for (int nt = 0; nt < 4; nt++)
            #pragma unroll
            for (int r = 0; r < 4; r++) acc[mt][nt][r] = 0.f;

    for (int i = 0; i < NC; i++) {
        cp_wait2();
        __syncthreads();
        const int p = i % 3;
        const float* As = sm + p * STAGE_FLOATS;
        const float* Bs = As + TILE_FLOATS;
        const float* Aw = As + (wm * 64 + lr) * ASTRIDE + lc;
        const float* Bw = Bs + (wn * 32 + lr) * ASTRIDE + lc;
        #pragma unroll
        for (int ks = 0; ks < 4; ks++) {
            uint32_t a[4][4], b[4][2];
            #pragma unroll
            for (int mt = 0; mt < 4; mt++) {
                const float* pa = Aw + mt * 16 * ASTRIDE + ks * 8;
                a[mt][0] = __float_as_uint(pa[0]);
                a[mt][1] = __float_as_uint(pa[8 * ASTRIDE]);
                a[mt][2] = __float_as_uint(pa[4]);
                a[mt][3] = __float_as_uint(pa[8 * ASTRIDE + 4]);
            }
            #pragma unroll
            for (int nt = 0; nt < 4; nt++) {
                const float* pb = Bw + nt * 8 * ASTRIDE + ks * 8;
                b[nt][0] = __float_as_uint(pb[0]);
                b[nt][1] = __float_as_uint(pb[4]);
            }
            #pragma unroll
            for (int mt = 0; mt < 4; mt++)
                #pragma unroll
                for (int nt = 0; nt < 4; nt++)
                    mma_tf32(acc[mt][nt], a[mt], b[nt]);
        }
        __syncthreads();
        if (i + GSTAGES < NC) {
            uint32_t so = sb + p * STAGE_BYTES;
            int k0 = (i + GSTAGES) * GBK;
            #pragma unroll
            for (int j = 0; j < 4; j++) cp_async16(so + aoff[j], ag[j] + k0);
            #pragma unroll
            for (int j = 0; j < 4; j++) cp_async16(so + boff[j], bg[j] + k0);
        }
        cp_commit();   // unconditional: keeps wait_group arithmetic exact at tail
    }

    // epilogue: c{0,1} at (row=lr, col=2*lc), c{2,3} at row+8
    #pragma unroll
    for (int mt = 0; mt < 4; mt++) {
        #pragma unroll
        for (int half = 0; half < 2; half++) {
            int row = brow0 + wm * 64 + mt * 16 + half * 8 + lr;
            float* crow = Cp + (size_t)row * N;
            #pragma unroll
            for (int nt = 0; nt < 4; nt++) {
                int col = bcol0 + wn * 32 + nt * 8 + lc * 2;
                float d0 = acc[mt][nt][half * 2 + 0];
                float d1 = acc[mt][nt][half * 2 + 1];
                if (EPI == 0) {
                    *reinterpret_cast<float2*>(crow + col) = make_float2(d0, d1);
                } else if (EPI == 1) {
                    float o0 = res[(size_t)row * N + col]     + d0 * scale[col];
                    float o1 = res[(size_t)row * N + col + 1] + d1 * scale[col + 1];
                    *reinterpret_cast<float2*>(crow + col) = make_float2(o0, o1);
                } else {
                    float u0 = upre[(size_t)row * N + col];
                    float u1 = upre[(size_t)row * N + col + 1];
                    float s0 = u0 / (1.0f + __expf(-u0));
                    float s1 = u1 / (1.0f + __expf(-u1));
                    *reinterpret_cast<float2*>(crow + col) = make_float2(s0 * d0, s1 * d1);
                }
            }
        }
    }
}

// ---------------- row RMSNorm over DIM=1024 ----------------
__global__ void rmsnorm_kernel(const float* __restrict__ x,
                               const float* __restrict__ w,
                               float* __restrict__ out, float eps) {
    int row = blockIdx.x;
    int tid = threadIdx.x;
    const float4* xr = reinterpret_cast<const float4*>(x + (size_t)row * DIM);
    float4 v = xr[tid];
    float ss = v.x*v.x + v.y*v.y + v.z*v.z + v.w*v.w;
    #pragma unroll
    for (int o = 16; o; o >>= 1) ss += __shfl_xor_sync(0xffffffffu, ss, o);
    __shared__ float red[8];
    __shared__ float stot;
    int lane = tid & 31, wid = tid >> 5;
    if (lane == 0) red[wid] = ss;
    __syncthreads();
    if (tid == 0) {
        float s = 0.f;
        #pragma unroll
        for (int i = 0; i < 8; i++) s += red[i];
        stot = rsqrtf(s * (1.0f / DIM) + eps);
    }
    __syncthreads();
    float sc = stot;
    const float4* wr = reinterpret_cast<const float4*>(w);
    float4 wv = wr[tid];
    float4 o4 = make_float4(v.x*sc*wv.x, v.y*sc*wv.y, v.z*sc*wv.z, v.w*sc*wv.w);
    reinterpret_cast<float4*>(out + (size_t)row * DIM)[tid] = o4;
}

// ---------------- per-head RMSNorm over HD=64 (in place) ----------------
__global__ void headnorm_kernel(float* __restrict__ q, const float* __restrict__ w) {
    int warp = threadIdx.x >> 5;
    int lane = threadIdx.x & 31;
    size_t r = (size_t)blockIdx.x * 4 + warp;
    float2* p = reinterpret_cast<float2*>(q + r * HD) + lane;
    float2 v = *p;
    float ss = v.x*v.x + v.y*v.y;
    #pragma unroll
    for (int o = 16; o; o >>= 1) ss += __shfl_xor_sync(0xffffffffu, ss, o);
    float sc = rsqrtf(ss * (1.0f / HD) + 1e-6f);
    float2 wv = reinterpret_cast<const float2*>(w)[lane];
    *p = make_float2(v.x*sc*wv.x, v.y*sc*wv.y);
}

// ---------------- sliding-window GQA attention (fp32) ----------------
__global__ void __launch_bounds__(64)
attn_kernel(const float* __restrict__ q, const float* __restrict__ k,
            const float* __restrict__ v, float* __restrict__ y) {
    __shared__ float Ksm[64 * HD];
    __shared__ float Vsm[64 * HD];
    float4* Ks4 = reinterpret_cast<float4*>(Ksm);
    float4* Vs4 = reinterpret_cast<float4*>(Vsm);

    const int m   = blockIdx.x;
    const int h   = blockIdx.y;
    const int b   = blockIdx.z;
    const int tid = threadIdx.x;
    const int qi  = m * 64 + tid;
    const int kvh = h >> 2;

    float4 qv[16];
    const float4* qp = reinterpret_cast<const float4*>(
        q + ((size_t)(b * TT + qi) * (NH * HD) + h * HD));
    #pragma unroll
    for (int d = 0; d < 16; d++) qv[d] = qp[d];

    float4 acc4[16];
    #pragma unroll
    for (int d = 0; d < 16; d++) acc4[d] = make_float4(0.f, 0.f, 0.f, 0.f);
    float mx = -INFINITY, l = 0.f;

    int t0 = (m >= 8) ? (m - 8) * 64 : 0;
    for (int tile = t0; tile <= m * 64; tile += 64) {
        const float4* kb = reinterpret_cast<const float4*>(
            k + ((size_t)(b * TT + tile) * (KVH * HD) + kvh * HD));
        const float4* vb = reinterpret_cast<const float4*>(
            v + ((size_t)(b * TT + tile) * (KVH * HD) + kvh * HD));
        const int rstride = (KVH * HD) / 4;
        #pragma unroll
        for (int i = 0; i < 16; i++) {
            int idx = i * 64 + tid;
            int r = idx >> 4, c = idx & 15;
            Ks4[idx] = kb[r * rstride + c];
            Vs4[idx] = vb[r * rstride + c];
        }
        __syncthreads();

        int jmax = qi - tile; if (jmax > 63) jmax = 63;
        int jmin = (qi - (WIN - 1)) - tile; if (jmin < 0) jmin = 0;
        for (int j = jmin; j <= jmax; j++) {
            const float4* kr = Ks4 + j * 16;
            float s = 0.f;
            #pragma unroll
            for (int d = 0; d < 16; d++) {
                float4 kk = kr[d];
                s += qv[d].x*kk.x + qv[d].y*kk.y + qv[d].z*kk.z + qv[d].w*kk.w;
            }
            s *= 0.125f;
            if (s > mx) {
                float corr = __expf(mx - s);
                mx = s;
                l *= corr;
                #pragma unroll
                for (int d = 0; d < 16; d++) {
                    acc4[d].x *= corr; acc4[d].y *= corr;
                    acc4[d].z *= corr; acc4[d].w *= corr;
                }
            }
            float p = __expf(s - mx);
            l += p;
            const float4* vr = Vs4 + j * 16;
            #pragma unroll
            for (int d = 0; d < 16; d++) {
                float4 vv = vr[d];
                acc4[d].x += p * vv.x; acc4[d].y += p * vv.y;
                acc4[d].z += p * vv.z; acc4[d].w += p * vv.w;
            }
        }
        __syncthreads();
    }

    float inv = 1.0f / l;
    float4* yp = reinterpret_cast<float4*>(
        y + ((size_t)(b * TT + qi) * (NH * HD) + h * HD));
    #pragma unroll
    for (int d = 0; d < 16; d++) {
        yp[d] = make_float4(acc4[d].x*inv, acc4[d].y*inv, acc4[d].z*inv, acc4[d].w*inv);
    }
}

// ---------------- launch ----------------
extern "C" void kernel_launch(void* const* d_in, const int* in_sizes, int n_in,
                              void* d_out, int out_size) {
    const float* x          = (const float*)d_in[0];
    const float* wq         = (const float*)d_in[1];
    const float* wk         = (const float*)d_in[2];
    const float* wv         = (const float*)d_in[3];
    const float* wo         = (const float*)d_in[4];
    const float* w1         = (const float*)d_in[5];
    const float* w2         = (const float*)d_in[6];
    const float* w3         = (const float*)d_in[7];
    const float* q_norm_w   = (const float*)d_in[8];
    const float* k_norm_w   = (const float*)d_in[9];
    const float* attn_norm_w= (const float*)d_in[10];
    const float* ffn_norm_w = (const float*)d_in[11];
    const float* attn_scale = (const float*)d_in[12];
    const float* ffn_scale  = (const float*)d_in[13];
    float* out = (float*)d_out;

    float *xn, *q, *k, *v, *y, *h, *u;
    cudaGetSymbolAddress((void**)&xn, g_xn);
    cudaGetSymbolAddress((void**)&q,  g_q);
    cudaGetSymbolAddress((void**)&k,  g_k);
    cudaGetSymbolAddress((void**)&v,  g_v);
    cudaGetSymbolAddress((void**)&y,  g_y);
    cudaGetSymbolAddress((void**)&h,  g_h);
    cudaGetSymbolAddress((void**)&u,  g_u);

    static bool attr_done = false;
    if (!attr_done) {
        cudaFuncSetAttribute(gemm_mma<0>, cudaFuncAttributeMaxDynamicSharedMemorySize, GSMEM_BYTES);
        cudaFuncSetAttribute(gemm_mma<1>, cudaFuncAttributeMaxDynamicSharedMemorySize, GSMEM_BYTES);
        cudaFuncSetAttribute(gemm_mma<2>, cudaFuncAttributeMaxDynamicSharedMemorySize, GSMEM_BYTES);
        attr_done = true;
    }

    const int MB = MROWS / GBM;   // 32

    // 1. xn = rmsnorm(x, attn_norm_w)
    rmsnorm_kernel<<<MROWS, 256>>>(x, attn_norm_w, xn, 1e-5f);

    // 2. q projection; k+v fused dual launch
    gemm_mma<0><<<dim3(DIM/GBN, MB), 256, GSMEM_BYTES>>>(
        xn, wq, q, DIM, DIM, nullptr, nullptr, nullptr, nullptr, nullptr);
    gemm_mma<0><<<dim3(4, MB), 256, GSMEM_BYTES>>>(
        xn, wk, k, DIM, KVH*HD, nullptr, nullptr, nullptr, wv, v);

    // 3. per-head q/k rmsnorm
    headnorm_kernel<<<(MROWS * NH) / 4, 128>>>(q, q_norm_w);
    headnorm_kernel<<<(MROWS * KVH) / 4, 128>>>(k, k_norm_w);

    // 4. sliding-window attention
    attn_kernel<<<dim3(TT/64, NH, BB), 64>>>(q, k, v, y);

    // 5. h = x + (y @ wo.T) * attn_scale
    gemm_mma<1><<<dim3(DIM/GBN, MB), 256, GSMEM_BYTES>>>(
        y, wo, h, DIM, DIM, x, attn_scale, nullptr, nullptr, nullptr);

    // 6. hn = rmsnorm(h, ffn_norm_w)
    rmsnorm_kernel<<<MROWS, 256>>>(h, ffn_norm_w, xn, 1e-5f);

    // 7. u = hn @ w1.T ; u = silu(u) * (hn @ w3.T)
    gemm_mma<0><<<dim3(HID/GBN, MB), 256, GSMEM_BYTES>>>(
        xn, w1, u, DIM, HID, nullptr, nullptr, nullptr, nullptr, nullptr);
    gemm_mma<2><<<dim3(HID/GBN, MB), 256, GSMEM_BYTES>>>(
        xn, w3, u, DIM, HID, nullptr, nullptr, u, nullptr, nullptr);

    // 8. out = h + (u @ w2.T) * ffn_scale
    gemm_mma<1><<<dim3(DIM/GBN, MB), 256, GSMEM_BYTES>>>(
        u, w2, out, HID, DIM, h, ffn_scale, nullptr, nullptr, nullptr);
}

// round 4
// speedup vs baseline: 2.5781x; 1.2031x over previous
#include <cuda_runtime.h>
#include <cuda_bf16.h>
#include <math.h>
#include <stdint.h>

// Problem constants
#define BB   2
#define TT   2048
#define MROWS (BB*TT)        // 4096
#define DIM  1024
#define HID  4096
#define NH   16
#define KVH  4
#define HD   64
#define WIN  512

// ---------------- scratch (device globals; no allocs allowed) ----------------
__device__ float g_xn[MROWS * DIM];
__device__ float g_q [MROWS * NH * HD];
__device__ float g_k [MROWS * KVH * HD];
__device__ float g_v [MROWS * KVH * HD];
__device__ float g_y [MROWS * NH * HD];
__device__ float g_h [MROWS * DIM];
__device__ float g_u [MROWS * HID];

// ================= helpers =================
__device__ __forceinline__ uint32_t smem_u32(const void* p) {
    uint32_t a;
    asm("{ .reg .u64 t; cvta.to.shared.u64 t, %1; cvt.u32.u64 %0, t; }" : "=r"(a) : "l"(p));
    return a;
}
__device__ __forceinline__ void cp_async16(uint32_t dst, const void* src) {
    asm volatile("cp.async.cg.shared.global [%0], [%1], 16;" :: "r"(dst), "l"(src) : "memory");
}
__device__ __forceinline__ void cp_commit() {
    asm volatile("cp.async.commit_group;" ::: "memory");
}
__device__ __forceinline__ void cp_wait1() {
    asm volatile("cp.async.wait_group 1;" ::: "memory");
}
__device__ __forceinline__ void mma_tf32(float* d, const uint32_t* a, const uint32_t* b) {
    asm volatile(
        "mma.sync.aligned.m16n8k8.row.col.f32.tf32.tf32.f32 "
        "{%0,%1,%2,%3}, {%4,%5,%6,%7}, {%8,%9}, {%0,%1,%2,%3};"
        : "+f"(d[0]), "+f"(d[1]), "+f"(d[2]), "+f"(d[3])
        : "r"(a[0]), "r"(a[1]), "r"(a[2]), "r"(a[3]), "r"(b[0]), "r"(b[1]));
}
// packed f32x2
typedef unsigned long long ull;
__device__ __forceinline__ ull pack2(float lo, float hi) {
    ull r; asm("mov.b64 %0, {%1,%2};" : "=l"(r) : "f"(lo), "f"(hi)); return r;
}
__device__ __forceinline__ void unpack2(ull v, float& lo, float& hi) {
    asm("mov.b64 {%0,%1}, %2;" : "=f"(lo), "=f"(hi) : "l"(v));
}
__device__ __forceinline__ ull fma2(ull a, ull b, ull c) {
    ull d; asm("fma.rn.f32x2 %0, %1, %2, %3;" : "=l"(d) : "l"(a), "l"(b), "l"(c)); return d;
}
__device__ __forceinline__ ull mul2(ull a, ull b) {
    ull d; asm("mul.rn.f32x2 %0, %1, %2;" : "=l"(d) : "l"(a), "l"(b)); return d;
}

// ================= tf32 mma.sync GEMM =================
// C[M,N] = A[M,K] @ W[N,K]^T.  BM=128, BN=128, BK=32, 2-stage cp.async, 2 CTAs/SM.
// 8 warps: wm = wid&1 (64 rows), wn = wid>>1 (32 cols).
// EPI: 0 none; 1 C = res + acc*scale[col]; 2 C = silu(upre)*acc
// If W2 != null: dual mode (blockIdx.x>>1 selects {W,C} vs {W2,C2}; bcol0=(x&1)*128)
#define GBM 128
#define GBN 128
#define GBK 32
#define ASTRIDE 36
#define TILE_FLOATS (GBM*ASTRIDE)       // 4608
#define STAGE_FLOATS (2*TILE_FLOATS)    // 9216
#define STAGE_BYTES (STAGE_FLOATS*4)    // 36864
#define GSMEM_BYTES (2*STAGE_BYTES)     // 73728

template<int EPI>
__global__ void __launch_bounds__(256, 2)
gemm_mma(const float* __restrict__ A, const float* __restrict__ W,
         float* __restrict__ C, int K, int N,
         const float* __restrict__ res, const float* __restrict__ scale,
         const float* __restrict__ upre,
         const float* __restrict__ W2, float* __restrict__ C2) {
    extern __shared__ float sm[];
    const uint32_t sb = smem_u32(sm);
    const int tid = threadIdx.x;
    const int wid = tid >> 5, lane = tid & 31;
    const int wm = wid & 1, wn = wid >> 1;
    const int lr = lane >> 2, lc = lane & 3;

    const float* Wp = W;
    float* Cp = C;
    int bcol0;
    if (W2 != nullptr) {
        if (blockIdx.x >> 1) { Wp = W2; Cp = C2; }
        bcol0 = (blockIdx.x & 1) * GBN;
    } else {
        bcol0 = blockIdx.x * GBN;
    }
    const int brow0 = blockIdx.y * GBM;

    // loader mapping: 4 float4 per thread per tile
    uint32_t aoff[4], boff[4];
    const float* ag[4];
    const float* bg[4];
    #pragma unroll
    for (int j = 0; j < 4; j++) {
        int f = tid + j * 256;
        int row = f >> 3, kc = (f & 7) * 4;
        aoff[j] = (uint32_t)(row * ASTRIDE + kc) * 4u;
        boff[j] = aoff[j] + TILE_FLOATS * 4u;
        ag[j] = A  + (size_t)(brow0 + row) * K + kc;
        bg[j] = Wp + (size_t)(bcol0 + row) * K + kc;
    }

    const int NC = K / GBK;

    // prologue: fill 2 stages
    #pragma unroll
    for (int s = 0; s < 2; s++) {
        uint32_t so = sb + s * STAGE_BYTES;
        int k0 = s * GBK;
        #pragma unroll
        for (int j = 0; j < 4; j++) cp_async16(so + aoff[j], ag[j] + k0);
        #pragma unroll
        for (int j = 0; j < 4; j++) cp_async16(so + boff[j], bg[j] + k0);
        cp_commit();
    }

    float acc[4][4][4];
    #pragma unroll
    for (int mt = 0; mt < 4; mt++)
        #pragma unroll
        for (int nt = 0; nt < 4; nt++)
            #pragma unroll
            for (int r = 0; r < 4; r++) acc[mt][nt][r] = 0.f;

    for (int i = 0; i < NC; i++) {
        cp_wait1();
        __syncthreads();
        const int p = i & 1;
        const float* As = sm + p * STAGE_FLOATS;
        const float* Bs = As + TILE_FLOATS;
        const float* Aw = As + (wm * 64 + lr) * ASTRIDE + lc;
        const float* Bw = Bs + (wn * 32 + lr) * ASTRIDE + lc;
        #pragma unroll
        for (int ks = 0; ks < 4; ks++) {
            uint32_t a[4][4], b[4][2];
            #pragma unroll
            for (int mt = 0; mt < 4; mt++) {
                const float* pa = Aw + mt * 16 * ASTRIDE + ks * 8;
                a[mt][0] = __float_as_uint(pa[0]);
                a[mt][1] = __float_as_uint(pa[8 * ASTRIDE]);
                a[mt][2] = __float_as_uint(pa[4]);
                a[mt][3] = __float_as_uint(pa[8 * ASTRIDE + 4]);
            }
            #pragma unroll
            for (int nt = 0; nt < 4; nt++) {
                const float* pb = Bw + nt * 8 * ASTRIDE + ks * 8;
                b[nt][0] = __float_as_uint(pb[0]);
                b[nt][1] = __float_as_uint(pb[4]);
            }
            #pragma unroll
            for (int mt = 0; mt < 4; mt++)
                #pragma unroll
                for (int nt = 0; nt < 4; nt++)
                    mma_tf32(acc[mt][nt], a[mt], b[nt]);
        }
        __syncthreads();
        if (i + 2 < NC) {
            uint32_t so = sb + p * STAGE_BYTES;
            int k0 = (i + 2) * GBK;
            #pragma unroll
            for (int j = 0; j < 4; j++) cp_async16(so + aoff[j], ag[j] + k0);
            #pragma unroll
            for (int j = 0; j < 4; j++) cp_async16(so + boff[j], bg[j] + k0);
        }
        cp_commit();   // unconditional: keeps wait_group arithmetic exact at tail
    }

    // epilogue: c{0,1} at (row=lr, col=2*lc), c{2,3} at row+8
    #pragma unroll
    for (int mt = 0; mt < 4; mt++) {
        #pragma unroll
        for (int half = 0; half < 2; half++) {
            int row = brow0 + wm * 64 + mt * 16 + half * 8 + lr;
            float* crow = Cp + (size_t)row * N;
            #pragma unroll
            for (int nt = 0; nt < 4; nt++) {
                int col = bcol0 + wn * 32 + nt * 8 + lc * 2;
                float d0 = acc[mt][nt][half * 2 + 0];
                float d1 = acc[mt][nt][half * 2 + 1];
                if (EPI == 0) {
                    *reinterpret_cast<float2*>(crow + col) = make_float2(d0, d1);
                } else if (EPI == 1) {
                    float o0 = res[(size_t)row * N + col]     + d0 * scale[col];
                    float o1 = res[(size_t)row * N + col + 1] + d1 * scale[col + 1];
                    *reinterpret_cast<float2*>(crow + col) = make_float2(o0, o1);
                } else {
                    float u0 = upre[(size_t)row * N + col];
                    float u1 = upre[(size_t)row * N + col + 1];
                    float s0 = u0 / (1.0f + __expf(-u0));
                    float s1 = u1 / (1.0f + __expf(-u1));
                    *reinterpret_cast<float2*>(crow + col) = make_float2(s0 * d0, s1 * d1);
                }
            }
        }
    }
}

// ---------------- row RMSNorm over DIM=1024 ----------------
__global__ void rmsnorm_kernel(const float* __restrict__ x,
                               const float* __restrict__ w,
                               float* __restrict__ out, float eps) {
    int row = blockIdx.x;
    int tid = threadIdx.x;
    const float4* xr = reinterpret_cast<const float4*>(x + (size_t)row * DIM);
    float4 v = xr[tid];
    float ss = v.x*v.x + v.y*v.y + v.z*v.z + v.w*v.w;
    #pragma unroll
    for (int o = 16; o; o >>= 1) ss += __shfl_xor_sync(0xffffffffu, ss, o);
    __shared__ float red[8];
    __shared__ float stot;
    int lane = tid & 31, wid = tid >> 5;
    if (lane == 0) red[wid] = ss;
    __syncthreads();
    if (tid == 0) {
        float s = 0.f;
        #pragma unroll
        for (int i = 0; i < 8; i++) s += red[i];
        stot = rsqrtf(s * (1.0f / DIM) + eps);
    }
    __syncthreads();
    float sc = stot;
    const float4* wr = reinterpret_cast<const float4*>(w);
    float4 wv = wr[tid];
    float4 o4 = make_float4(v.x*sc*wv.x, v.y*sc*wv.y, v.z*sc*wv.z, v.w*sc*wv.w);
    reinterpret_cast<float4*>(out + (size_t)row * DIM)[tid] = o4;
}

// ---------------- per-head RMSNorm over HD=64 (in place, for K) ----------------
__global__ void headnorm_kernel(float* __restrict__ q, const float* __restrict__ w) {
    int warp = threadIdx.x >> 5;
    int lane = threadIdx.x & 31;
    size_t r = (size_t)blockIdx.x * 4 + warp;
    float2* p = reinterpret_cast<float2*>(q + r * HD) + lane;
    float2 v = *p;
    float ss = v.x*v.x + v.y*v.y;
    #pragma unroll
    for (int o = 16; o; o >>= 1) ss += __shfl_xor_sync(0xffffffffu, ss, o);
    float sc = rsqrtf(ss * (1.0f / HD) + 1e-6f);
    float2 wv = reinterpret_cast<const float2*>(w)[lane];
    *p = make_float2(v.x*sc*wv.x, v.y*sc*wv.y);
}

// ---------------- sliding-window GQA attention (f32x2, 4 heads/block) ----------
// grid (T/64, KVH, B), 256 threads: tid>>6 = head-in-group, tid&63 = query.
// Q head-RMSNorm fused into the register load (scale folded with 1/sqrt(HD)).
__global__ void __launch_bounds__(256, 1)
attn_kernel(const float* __restrict__ q, const float* __restrict__ k,
            const float* __restrict__ v, float* __restrict__ y,
            const float* __restrict__ qnw) {
    __shared__ float Ksm[64 * HD];
    __shared__ float Vsm[64 * HD];
    __shared__ float Wsm[HD];
    float4* Ks4 = reinterpret_cast<float4*>(Ksm);
    float4* Vs4 = reinterpret_cast<float4*>(Vsm);

    const int m   = blockIdx.x;
    const int kvh = blockIdx.y;
    const int b   = blockIdx.z;
    const int tid = threadIdx.x;
    const int hq  = tid >> 6;
    const int qt  = tid & 63;
    const int h   = kvh * 4 + hq;
    const int qi  = m * 64 + qt;

    if (tid < HD) Wsm[tid] = qnw[tid];
    __syncthreads();

    // load q row; fused RMSNorm (eps 1e-6) with 1/sqrt(HD)=0.125 folded in
    const float4* qp = reinterpret_cast<const float4*>(
        q + ((size_t)(b * TT + qi) * (NH * HD) + h * HD));
    float4 qv[16];
    float ssq = 0.f;
    #pragma unroll
    for (int d = 0; d < 16; d++) {
        qv[d] = qp[d];
        ssq += qv[d].x*qv[d].x + qv[d].y*qv[d].y + qv[d].z*qv[d].z + qv[d].w*qv[d].w;
    }
    float qsc = rsqrtf(ssq * (1.0f / HD) + 1e-6f) * 0.125f;
    ull q2[32];
    #pragma unroll
    for (int d = 0; d < 16; d++) {
        q2[2*d]   = pack2(qv[d].x * qsc * Wsm[4*d],   qv[d].y * qsc * Wsm[4*d+1]);
        q2[2*d+1] = pack2(qv[d].z * qsc * Wsm[4*d+2], qv[d].w * qsc * Wsm[4*d+3]);
    }

    ull acc2[32];
    #pragma unroll
    for (int d = 0; d < 32; d++) acc2[d] = 0ull;
    float mx = -INFINITY, l = 0.f;

    const int rstride = (KVH * HD) / 4;   // 64 float4 per source row
    int t0 = (m >= 8) ? (m - 8) * 64 : 0;
    for (int tile = t0; tile <= m * 64; tile += 64) {
        const float4* kb = reinterpret_cast<const float4*>(
            k + ((size_t)(b * TT + tile) * (KVH * HD) + kvh * HD));
        const float4* vb = reinterpret_cast<const float4*>(
            v + ((size_t)(b * TT + tile) * (KVH * HD) + kvh * HD));
        __syncthreads();
        #pragma unroll
        for (int i = 0; i < 4; i++) {
            int idx = i * 256 + tid;          // 1024 float4 = 64 rows x 16
            int r = idx >> 4, c = idx & 15;
            Ks4[idx] = kb[r * rstride + c];
            Vs4[idx] = vb[r * rstride + c];
        }
        __syncthreads();

        int jmax = qi - tile; if (jmax > 63) jmax = 63;
        int jmin = (qi - (WIN - 1)) - tile; if (jmin < 0) jmin = 0;
        for (int j = jmin; j <= jmax; j++) {
            const ull* kr = reinterpret_cast<const ull*>(Ksm + j * HD);
            ull s2 = 0ull;
            #pragma unroll
            for (int d = 0; d < 32; d++) s2 = fma2(q2[d], kr[d], s2);
            float slo, shi; unpack2(s2, slo, shi);
            float s = slo + shi;
            if (s > mx) {
                float corr = __expf(mx - s);   // 0 on first key
                mx = s;
                l *= corr;
                ull c2 = pack2(corr, corr);
                #pragma unroll
                for (int d = 0; d < 32; d++) acc2[d] = mul2(acc2[d], c2);
            }
            float p = __expf(s - mx);
            l += p;
            ull p2 = pack2(p, p);
            const ull* vr = reinterpret_cast<const ull*>(Vsm + j * HD);
            #pragma unroll
            for (int d = 0; d < 32; d++) acc2[d] = fma2(p2, vr[d], acc2[d]);
        }
    }

    float inv = 1.0f / l;
    float2* yp = reinterpret_cast<float2*>(
        y + ((size_t)(b * TT + qi) * (NH * HD) + h * HD));
    #pragma unroll
    for (int d = 0; d < 32; d++) {
        float lo, hi; unpack2(acc2[d], lo, hi);
        yp[d] = make_float2(lo * inv, hi * inv);
    }
}

// ---------------- launch ----------------
extern "C" void kernel_launch(void* const* d_in, const int* in_sizes, int n_in,
                              void* d_out, int out_size) {
    const float* x          = (const float*)d_in[0];
    const float* wq         = (const float*)d_in[1];
    const float* wk         = (const float*)d_in[2];
    const float* wv         = (const float*)d_in[3];
    const float* wo         = (const float*)d_in[4];
    const float* w1         = (const float*)d_in[5];
    const float* w2         = (const float*)d_in[6];
    const float* w3         = (const float*)d_in[7];
    const float* q_norm_w   = (const float*)d_in[8];
    const float* k_norm_w   = (const float*)d_in[9];
    const float* attn_norm_w= (const float*)d_in[10];
    const float* ffn_norm_w = (const float*)d_in[11];
    const float* attn_scale = (const float*)d_in[12];
    const float* ffn_scale  = (const float*)d_in[13];
    float* out = (float*)d_out;

    float *xn, *q, *k, *v, *y, *h, *u;
    cudaGetSymbolAddress((void**)&xn, g_xn);
    cudaGetSymbolAddress((void**)&q,  g_q);
    cudaGetSymbolAddress((void**)&k,  g_k);
    cudaGetSymbolAddress((void**)&v,  g_v);
    cudaGetSymbolAddress((void**)&y,  g_y);
    cudaGetSymbolAddress((void**)&h,  g_h);
    cudaGetSymbolAddress((void**)&u,  g_u);

    static bool attr_done = false;
    if (!attr_done) {
        cudaFuncSetAttribute(gemm_mma<0>, cudaFuncAttributeMaxDynamicSharedMemorySize, GSMEM_BYTES);
        cudaFuncSetAttribute(gemm_mma<1>, cudaFuncAttributeMaxDynamicSharedMemorySize, GSMEM_BYTES);
        cudaFuncSetAttribute(gemm_mma<2>, cudaFuncAttributeMaxDynamicSharedMemorySize, GSMEM_BYTES);
        attr_done = true;
    }

    const int MB = MROWS / GBM;   // 32

    // 1. xn = rmsnorm(x, attn_norm_w)
    rmsnorm_kernel<<<MROWS, 256>>>(x, attn_norm_w, xn, 1e-5f);

    // 2. q projection; k+v fused dual launch
    gemm_mma<0><<<dim3(DIM/GBN, MB), 256, GSMEM_BYTES>>>(
        xn, wq, q, DIM, DIM, nullptr, nullptr, nullptr, nullptr, nullptr);
    gemm_mma<0><<<dim3(4, MB), 256, GSMEM_BYTES>>>(
        xn, wk, k, DIM, KVH*HD, nullptr, nullptr, nullptr, wv, v);

    // 3. k head-rmsnorm (q norm fused into attention)
    headnorm_kernel<<<(MROWS * KVH) / 4, 128>>>(k, k_norm_w);

    // 4. sliding-window attention (4 heads/block share KV)
    attn_kernel<<<dim3(TT/64, KVH, BB), 256>>>(q, k, v, y, q_norm_w);

    // 5. h = x + (y @ wo.T) * attn_scale
    gemm_mma<1><<<dim3(DIM/GBN, MB), 256, GSMEM_BYTES>>>(
        y, wo, h, DIM, DIM, x, attn_scale, nullptr, nullptr, nullptr);

    // 6. hn = rmsnorm(h, ffn_norm_w)
    rmsnorm_kernel<<<MROWS, 256>>>(h, ffn_norm_w, xn, 1e-5f);

    // 7. u = hn @ w1.T ; u = silu(u) * (hn @ w3.T)
    gemm_mma<0><<<dim3(HID/GBN, MB), 256, GSMEM_BYTES>>>(
        xn, w1, u, DIM, HID, nullptr, nullptr, nullptr, nullptr, nullptr);
    gemm_mma<2><<<dim3(HID/GBN, MB), 256, GSMEM_BYTES>>>(
        xn, w3, u, DIM, HID, nullptr, nullptr, u, nullptr, nullptr);

    // 8. out = h + (u @ w2.T) * ffn_scale
    gemm_mma<1><<<dim3(DIM/GBN, MB), 256, GSMEM_BYTES>>>(
        u, w2, out, HID, DIM, h, ffn_scale, nullptr, nullptr, nullptr);
}

// round 5
// speedup vs baseline: 3.4141x; 1.3243x over previous
#include <cuda_runtime.h>
#include <cuda_fp16.h>
#include <math.h>
#include <stdint.h>

// Problem constants
#define BB   2
#define TT   2048
#define MROWS (BB*TT)        // 4096
#define DIM  1024
#define HID  4096
#define NH   16
#define KVH  4
#define HD   64
#define WIN  512

// ---------------- scratch (device globals; no allocs allowed) ----------------
__device__ float g_q [MROWS * NH * HD];
__device__ float g_k [MROWS * KVH * HD];
__device__ float g_v [MROWS * KVH * HD];
__device__ float g_h [MROWS * DIM];
// fp16 buffers
__device__ __half g_xnh[MROWS * DIM];     // rmsnorm out (xn / hn)
__device__ __half g_yh [MROWS * NH * HD]; // attention out
__device__ __half g_uh [MROWS * HID];     // w1 out (pre-activation)
__device__ __half g_ph [MROWS * HID];     // silu(u)*g
// fp16 weights
__device__ __half g_wq[NH*HD * DIM];
__device__ __half g_wk[KVH*HD * DIM];
__device__ __half g_wv[KVH*HD * DIM];
__device__ __half g_wo[DIM * NH*HD];
__device__ __half g_w1[HID * DIM];
__device__ __half g_w2[DIM * HID];
__device__ __half g_w3[HID * DIM];

// ================= helpers =================
__device__ __forceinline__ uint32_t smem_u32(const void* p) {
    uint32_t a;
    asm("{ .reg .u64 t; cvta.to.shared.u64 t, %1; cvt.u32.u64 %0, t; }" : "=r"(a) : "l"(p));
    return a;
}
__device__ __forceinline__ void cp_async16(uint32_t dst, const void* src) {
    asm volatile("cp.async.cg.shared.global [%0], [%1], 16;" :: "r"(dst), "l"(src) : "memory");
}
__device__ __forceinline__ void cp_commit() {
    asm volatile("cp.async.commit_group;" ::: "memory");
}
__device__ __forceinline__ void cp_wait1() {
    asm volatile("cp.async.wait_group 1;" ::: "memory");
}
__device__ __forceinline__ void mma_f16(float* d, const uint32_t* a, const uint32_t* b) {
    asm volatile(
        "mma.sync.aligned.m16n8k16.row.col.f32.f16.f16.f32 "
        "{%0,%1,%2,%3}, {%4,%5,%6,%7}, {%8,%9}, {%0,%1,%2,%3};"
        : "+f"(d[0]), "+f"(d[1]), "+f"(d[2]), "+f"(d[3])
        : "r"(a[0]), "r"(a[1]), "r"(a[2]), "r"(a[3]), "r"(b[0]), "r"(b[1]));
}
// packed f32x2
typedef unsigned long long ull;
__device__ __forceinline__ ull pack2(float lo, float hi) {
    ull r; asm("mov.b64 %0, {%1,%2};" : "=l"(r) : "f"(lo), "f"(hi)); return r;
}
__device__ __forceinline__ void unpack2(ull v, float& lo, float& hi) {
    asm("mov.b64 {%0,%1}, %2;" : "=f"(lo), "=f"(hi) : "l"(v));
}
__device__ __forceinline__ ull fma2(ull a, ull b, ull c) {
    ull d; asm("fma.rn.f32x2 %0, %1, %2, %3;" : "=l"(d) : "l"(a), "l"(b), "l"(c)); return d;
}
__device__ __forceinline__ ull mul2(ull a, ull b) {
    ull d; asm("mul.rn.f32x2 %0, %1, %2;" : "=l"(d) : "l"(a), "l"(b)); return d;
}

// ---------------- fp32 -> fp16 convert ----------------
__global__ void f2h_kernel(const float* __restrict__ in, __half* __restrict__ out, int n4) {
    int i = blockIdx.x * blockDim.x + threadIdx.x;
    if (i < n4) {
        float4 v = reinterpret_cast<const float4*>(in)[i];
        __half2 h0 = __floats2half2_rn(v.x, v.y);
        __half2 h1 = __floats2half2_rn(v.z, v.w);
        reinterpret_cast<__half2*>(out)[2*i]   = h0;
        reinterpret_cast<__half2*>(out)[2*i+1] = h1;
    }
}

// ================= fp16 mma.sync GEMM =================
// C[M,N] = A[M,K] @ W[N,K]^T, fp16 in, fp32 accum. BM=128,BN=128,BK=32 halfs.
// 2-stage cp.async, 2 CTAs/SM. 8 warps: wm=wid&1 (64 rows), wn=wid>>1 (32 cols).
// EPI: 0 plain store (TO); 1 C=res+acc*scale[col] (TO=float); 2 C=silu(upre)*acc (TO=__half)
// If W2!=null: dual mode (blockIdx.x>>1 selects {W,C} vs {W2,C2}; bcol0=(x&1)*128)
#define GBM 128
#define GBN 128
#define GBK 32
#define HSTRIDE 40                      // halfs per SMEM row (20 words: conflict-free)
#define TILE_HALFS (GBM*HSTRIDE)        // 5120
#define STAGE_HALFS (2*TILE_HALFS)      // 10240
#define STAGE_BYTES (STAGE_HALFS*2)     // 20480
#define GSMEM_BYTES (2*STAGE_BYTES)     // 40960

template<int EPI, typename TO>
__global__ void __launch_bounds__(256, 2)
gemm_mma(const __half* __restrict__ A, const __half* __restrict__ W,
         TO* __restrict__ C, int K, int N,
         const float* __restrict__ res, const float* __restrict__ scale,
         const __half* __restrict__ upre,
         const __half* __restrict__ W2, TO* __restrict__ C2) {
    extern __shared__ __half sm[];
    const uint32_t sb = smem_u32(sm);
    const int tid = threadIdx.x;
    const int wid = tid >> 5, lane = tid & 31;
    const int wm = wid & 1, wn = wid >> 1;
    const int lr = lane >> 2, lc = lane & 3;

    const __half* Wp = W;
    TO* Cp = C;
    int bcol0;
    if (W2 != nullptr) {
        if (blockIdx.x >> 1) { Wp = W2; Cp = C2; }
        bcol0 = (blockIdx.x & 1) * GBN;
    } else {
        bcol0 = blockIdx.x * GBN;
    }
    const int brow0 = blockIdx.y * GBM;

    // loader: 2 chunks (16B = 8 halfs) per matrix per thread
    uint32_t aoff[2], boff[2];
    const __half* ag[2];
    const __half* bg[2];
    #pragma unroll
    for (int j = 0; j < 2; j++) {
        int f = tid + j * 256;
        int row = f >> 2, kc = (f & 3) * 8;
        aoff[j] = (uint32_t)(row * HSTRIDE + kc) * 2u;
        boff[j] = aoff[j] + TILE_HALFS * 2u;
        ag[j] = A  + (size_t)(brow0 + row) * K + kc;
        bg[j] = Wp + (size_t)(bcol0 + row) * K + kc;
    }

    const int NC = K / GBK;

    #pragma unroll
    for (int s = 0; s < 2; s++) {
        uint32_t so = sb + s * STAGE_BYTES;
        int k0 = s * GBK;
        #pragma unroll
        for (int j = 0; j < 2; j++) cp_async16(so + aoff[j], ag[j] + k0);
        #pragma unroll
        for (int j = 0; j < 2; j++) cp_async16(so + boff[j], bg[j] + k0);
        cp_commit();
    }

    float acc[4][4][4];
    #pragma unroll
    for (int mt = 0; mt < 4; mt++)
        #pragma unroll
        for (int nt = 0; nt < 4; nt++)
            #pragma unroll
            for (int r = 0; r < 4; r++) acc[mt][nt][r] = 0.f;

    for (int i = 0; i < NC; i++) {
        cp_wait1();
        __syncthreads();
        const int p = i & 1;
        const __half* As = sm + p * STAGE_HALFS;
        const __half* Bs = As + TILE_HALFS;
        const __half* Aw = As + (wm * 64 + lr) * HSTRIDE + lc * 2;
        const __half* Bw = Bs + (wn * 32 + lr) * HSTRIDE + lc * 2;
        #pragma unroll
        for (int ks = 0; ks < 2; ks++) {
            uint32_t a[4][4], b[4][2];
            #pragma unroll
            for (int mt = 0; mt < 4; mt++) {
                const __half* pa = Aw + mt * 16 * HSTRIDE + ks * 16;
                a[mt][0] = *reinterpret_cast<const uint32_t*>(pa);
                a[mt][1] = *reinterpret_cast<const uint32_t*>(pa + 8 * HSTRIDE);
                a[mt][2] = *reinterpret_cast<const uint32_t*>(pa + 8);
                a[mt][3] = *reinterpret_cast<const uint32_t*>(pa + 8 * HSTRIDE + 8);
            }
            #pragma unroll
            for (int nt = 0; nt < 4; nt++) {
                const __half* pb = Bw + nt * 8 * HSTRIDE + ks * 16;
                b[nt][0] = *reinterpret_cast<const uint32_t*>(pb);
                b[nt][1] = *reinterpret_cast<const uint32_t*>(pb + 8);
            }
            #pragma unroll
            for (int mt = 0; mt < 4; mt++)
                #pragma unroll
                for (int nt = 0; nt < 4; nt++)
                    mma_f16(acc[mt][nt], a[mt], b[nt]);
        }
        __syncthreads();
        if (i + 2 < NC) {
            uint32_t so = sb + p * STAGE_BYTES;
            int k0 = (i + 2) * GBK;
            #pragma unroll
            for (int j = 0; j < 2; j++) cp_async16(so + aoff[j], ag[j] + k0);
            #pragma unroll
            for (int j = 0; j < 2; j++) cp_async16(so + boff[j], bg[j] + k0);
        }
        cp_commit();
    }

    // epilogue: c{0,1} at (row=lr, col=2*lc), c{2,3} at row+8
    #pragma unroll
    for (int mt = 0; mt < 4; mt++) {
        #pragma unroll
        for (int half = 0; half < 2; half++) {
            int row = brow0 + wm * 64 + mt * 16 + half * 8 + lr;
            TO* crow = Cp + (size_t)row * N;
            #pragma unroll
            for (int nt = 0; nt < 4; nt++) {
                int col = bcol0 + wn * 32 + nt * 8 + lc * 2;
                float d0 = acc[mt][nt][half * 2 + 0];
                float d1 = acc[mt][nt][half * 2 + 1];
                if (EPI == 0) {
                    if (sizeof(TO) == 2) {
                        *reinterpret_cast<__half2*>((__half*)crow + col) = __floats2half2_rn(d0, d1);
                    } else {
                        *reinterpret_cast<float2*>((float*)crow + col) = make_float2(d0, d1);
                    }
                } else if (EPI == 1) {
                    float o0 = res[(size_t)row * N + col]     + d0 * scale[col];
                    float o1 = res[(size_t)row * N + col + 1] + d1 * scale[col + 1];
                    *reinterpret_cast<float2*>((float*)crow + col) = make_float2(o0, o1);
                } else {
                    float u0 = __half2float(upre[(size_t)row * N + col]);
                    float u1 = __half2float(upre[(size_t)row * N + col + 1]);
                    float s0 = u0 / (1.0f + __expf(-u0));
                    float s1 = u1 / (1.0f + __expf(-u1));
                    *reinterpret_cast<__half2*>((__half*)crow + col) = __floats2half2_rn(s0 * d0, s1 * d1);
                }
            }
        }
    }
}

// ---------------- row RMSNorm over DIM=1024 (fp32 in, fp16 out) ----------------
__global__ void rmsnorm_kernel(const float* __restrict__ x,
                               const float* __restrict__ w,
                               __half* __restrict__ out, float eps) {
    int row = blockIdx.x;
    int tid = threadIdx.x;
    const float4* xr = reinterpret_cast<const float4*>(x + (size_t)row * DIM);
    float4 v = xr[tid];
    float ss = v.x*v.x + v.y*v.y + v.z*v.z + v.w*v.w;
    #pragma unroll
    for (int o = 16; o; o >>= 1) ss += __shfl_xor_sync(0xffffffffu, ss, o);
    __shared__ float red[8];
    __shared__ float stot;
    int lane = tid & 31, wid = tid >> 5;
    if (lane == 0) red[wid] = ss;
    __syncthreads();
    if (tid == 0) {
        float s = 0.f;
        #pragma unroll
        for (int i = 0; i < 8; i++) s += red[i];
        stot = rsqrtf(s * (1.0f / DIM) + eps);
    }
    __syncthreads();
    float sc = stot;
    const float4* wr = reinterpret_cast<const float4*>(w);
    float4 wv = wr[tid];
    __half2 h0 = __floats2half2_rn(v.x*sc*wv.x, v.y*sc*wv.y);
    __half2 h1 = __floats2half2_rn(v.z*sc*wv.z, v.w*sc*wv.w);
    __half2* op = reinterpret_cast<__half2*>(out + (size_t)row * DIM) + tid * 2;
    op[0] = h0; op[1] = h1;
}

// ---------------- per-head RMSNorm over HD=64 (in place, for K) ----------------
__global__ void headnorm_kernel(float* __restrict__ q, const float* __restrict__ w) {
    int warp = threadIdx.x >> 5;
    int lane = threadIdx.x & 31;
    size_t r = (size_t)blockIdx.x * 4 + warp;
    float2* p = reinterpret_cast<float2*>(q + r * HD) + lane;
    float2 v = *p;
    float ss = v.x*v.x + v.y*v.y;
    #pragma unroll
    for (int o = 16; o; o >>= 1) ss += __shfl_xor_sync(0xffffffffu, ss, o);
    float sc = rsqrtf(ss * (1.0f / HD) + 1e-6f);
    float2 wv = reinterpret_cast<const float2*>(w)[lane];
    *p = make_float2(v.x*sc*wv.x, v.y*sc*wv.y);
}

// ---------------- sliding-window GQA attention (f32x2, 4 heads/block) ----------
// grid (T/64, KVH, B), 256 threads. Writes fp16 y.
__global__ void __launch_bounds__(256, 1)
attn_kernel(const float* __restrict__ q, const float* __restrict__ k,
            const float* __restrict__ v, __half* __restrict__ y,
            const float* __restrict__ qnw) {
    __shared__ float Ksm[64 * HD];
    __shared__ float Vsm[64 * HD];
    __shared__ float Wsm[HD];
    float4* Ks4 = reinterpret_cast<float4*>(Ksm);
    float4* Vs4 = reinterpret_cast<float4*>(Vsm);

    const int m   = blockIdx.x;
    const int kvh = blockIdx.y;
    const int b   = blockIdx.z;
    const int tid = threadIdx.x;
    const int hq  = tid >> 6;
    const int qt  = tid & 63;
    const int h   = kvh * 4 + hq;
    const int qi  = m * 64 + qt;

    if (tid < HD) Wsm[tid] = qnw[tid];
    __syncthreads();

    const float4* qp = reinterpret_cast<const float4*>(
        q + ((size_t)(b * TT + qi) * (NH * HD) + h * HD));
    float4 qv[16];
    float ssq = 0.f;
    #pragma unroll
    for (int d = 0; d < 16; d++) {
        qv[d] = qp[d];
        ssq += qv[d].x*qv[d].x + qv[d].y*qv[d].y + qv[d].z*qv[d].z + qv[d].w*qv[d].w;
    }
    float qsc = rsqrtf(ssq * (1.0f / HD) + 1e-6f) * 0.125f;
    ull q2[32];
    #pragma unroll
    for (int d = 0; d < 16; d++) {
        q2[2*d]   = pack2(qv[d].x * qsc * Wsm[4*d],   qv[d].y * qsc * Wsm[4*d+1]);
        q2[2*d+1] = pack2(qv[d].z * qsc * Wsm[4*d+2], qv[d].w * qsc * Wsm[4*d+3]);
    }

    ull acc2[32];
    #pragma unroll
    for (int d = 0; d < 32; d++) acc2[d] = 0ull;
    float mx = -INFINITY, l = 0.f;

    const int rstride = (KVH * HD) / 4;
    int t0 = (m >= 8) ? (m - 8) * 64 : 0;
    for (int tile = t0; tile <= m * 64; tile += 64) {
        const float4* kb = reinterpret_cast<const float4*>(
            k + ((size_t)(b * TT + tile) * (KVH * HD) + kvh * HD));
        const float4* vb = reinterpret_cast<const float4*>(
            v + ((size_t)(b * TT + tile) * (KVH * HD) + kvh * HD));
        __syncthreads();
        #pragma unroll
        for (int i = 0; i < 4; i++) {
            int idx = i * 256 + tid;
            int r = idx >> 4, c = idx & 15;
            Ks4[idx] = kb[r * rstride + c];
            Vs4[idx] = vb[r * rstride + c];
        }
        __syncthreads();

        int jmax = qi - tile; if (jmax > 63) jmax = 63;
        int jmin = (qi - (WIN - 1)) - tile; if (jmin < 0) jmin = 0;
        for (int j = jmin; j <= jmax; j++) {
            const ull* kr = reinterpret_cast<const ull*>(Ksm + j * HD);
            ull s2 = 0ull;
            #pragma unroll
            for (int d = 0; d < 32; d++) s2 = fma2(q2[d], kr[d], s2);
            float slo, shi; unpack2(s2, slo, shi);
            float s = slo + shi;
            if (s > mx) {
                float corr = __expf(mx - s);
                mx = s;
                l *= corr;
                ull c2 = pack2(corr, corr);
                #pragma unroll
                for (int d = 0; d < 32; d++) acc2[d] = mul2(acc2[d], c2);
            }
            float p = __expf(s - mx);
            l += p;
            ull p2 = pack2(p, p);
            const ull* vr = reinterpret_cast<const ull*>(Vsm + j * HD);
            #pragma unroll
            for (int d = 0; d < 32; d++) acc2[d] = fma2(p2, vr[d], acc2[d]);
        }
    }

    float inv = 1.0f / l;
    __half2* yp = reinterpret_cast<__half2*>(
        y + ((size_t)(b * TT + qi) * (NH * HD) + h * HD));
    #pragma unroll
    for (int d = 0; d < 32; d++) {
        float lo, hi; unpack2(acc2[d], lo, hi);
        yp[d] = __floats2half2_rn(lo * inv, hi * inv);
    }
}

// ---------------- launch ----------------
extern "C" void kernel_launch(void* const* d_in, const int* in_sizes, int n_in,
                              void* d_out, int out_size) {
    const float* x          = (const float*)d_in[0];
    const float* wq         = (const float*)d_in[1];
    const float* wk         = (const float*)d_in[2];
    const float* wv         = (const float*)d_in[3];
    const float* wo         = (const float*)d_in[4];
    const float* w1         = (const float*)d_in[5];
    const float* w2         = (const float*)d_in[6];
    const float* w3         = (const float*)d_in[7];
    const float* q_norm_w   = (const float*)d_in[8];
    const float* k_norm_w   = (const float*)d_in[9];
    const float* attn_norm_w= (const float*)d_in[10];
    const float* ffn_norm_w = (const float*)d_in[11];
    const float* attn_scale = (const float*)d_in[12];
    const float* ffn_scale  = (const float*)d_in[13];
    float* out = (float*)d_out;

    float *q, *k, *v, *h;
    __half *xnh, *yh, *uh, *ph, *hwq, *hwk, *hwv, *hwo, *hw1, *hw2, *hw3;
    cudaGetSymbolAddress((void**)&q,  g_q);
    cudaGetSymbolAddress((void**)&k,  g_k);
    cudaGetSymbolAddress((void**)&v,  g_v);
    cudaGetSymbolAddress((void**)&h,  g_h);
    cudaGetSymbolAddress((void**)&xnh, g_xnh);
    cudaGetSymbolAddress((void**)&yh,  g_yh);
    cudaGetSymbolAddress((void**)&uh,  g_uh);
    cudaGetSymbolAddress((void**)&ph,  g_ph);
    cudaGetSymbolAddress((void**)&hwq, g_wq);
    cudaGetSymbolAddress((void**)&hwk, g_wk);
    cudaGetSymbolAddress((void**)&hwv, g_wv);
    cudaGetSymbolAddress((void**)&hwo, g_wo);
    cudaGetSymbolAddress((void**)&hw1, g_w1);
    cudaGetSymbolAddress((void**)&hw2, g_w2);
    cudaGetSymbolAddress((void**)&hw3, g_w3);

    static bool attr_done = false;
    if (!attr_done) {
        cudaFuncSetAttribute((const void*)gemm_mma<0, float>,  cudaFuncAttributeMaxDynamicSharedMemorySize, GSMEM_BYTES);
        cudaFuncSetAttribute((const void*)gemm_mma<0, __half>, cudaFuncAttributeMaxDynamicSharedMemorySize, GSMEM_BYTES);
        cudaFuncSetAttribute((const void*)gemm_mma<1, float>,  cudaFuncAttributeMaxDynamicSharedMemorySize, GSMEM_BYTES);
        cudaFuncSetAttribute((const void*)gemm_mma<2, __half>, cudaFuncAttributeMaxDynamicSharedMemorySize, GSMEM_BYTES);
        attr_done = true;
    }

    // 0. convert weights fp32 -> fp16
    {
        const int T = 256;
        f2h_kernel<<<(NH*HD*DIM/4 + T-1)/T, T>>>(wq, hwq, NH*HD*DIM/4);
        f2h_kernel<<<(KVH*HD*DIM/4 + T-1)/T, T>>>(wk, hwk, KVH*HD*DIM/4);
        f2h_kernel<<<(KVH*HD*DIM/4 + T-1)/T, T>>>(wv, hwv, KVH*HD*DIM/4);
        f2h_kernel<<<(DIM*NH*HD/4 + T-1)/T, T>>>(wo, hwo, DIM*NH*HD/4);
        f2h_kernel<<<(HID*DIM/4 + T-1)/T, T>>>(w1, hw1, HID*DIM/4);
        f2h_kernel<<<(DIM*HID/4 + T-1)/T, T>>>(w2, hw2, DIM*HID/4);
        f2h_kernel<<<(HID*DIM/4 + T-1)/T, T>>>(w3, hw3, HID*DIM/4);
    }

    const int MB = MROWS / GBM;   // 32

    // 1. xn = rmsnorm(x, attn_norm_w) -> fp16
    rmsnorm_kernel<<<MROWS, 256>>>(x, attn_norm_w, xnh, 1e-5f);

    // 2. q projection; k+v fused dual launch (fp32 out)
    gemm_mma<0, float><<<dim3(DIM/GBN, MB), 256, GSMEM_BYTES>>>(
        xnh, hwq, q, DIM, DIM, nullptr, nullptr, nullptr, nullptr, nullptr);
    gemm_mma<0, float><<<dim3(4, MB), 256, GSMEM_BYTES>>>(
        xnh, hwk, k, DIM, KVH*HD, nullptr, nullptr, nullptr, hwv, v);

    // 3. k head-rmsnorm (q norm fused into attention)
    headnorm_kernel<<<(MROWS * KVH) / 4, 128>>>(k, k_norm_w);

    // 4. sliding-window attention -> fp16 y
    attn_kernel<<<dim3(TT/64, KVH, BB), 256>>>(q, k, v, yh, q_norm_w);

    // 5. h = x + (y @ wo.T) * attn_scale   (fp32 out)
    gemm_mma<1, float><<<dim3(DIM/GBN, MB), 256, GSMEM_BYTES>>>(
        yh, hwo, h, DIM, DIM, x, attn_scale, nullptr, nullptr, nullptr);

    // 6. hn = rmsnorm(h, ffn_norm_w) -> fp16
    rmsnorm_kernel<<<MROWS, 256>>>(h, ffn_norm_w, xnh, 1e-5f);

    // 7. u = hn @ w1.T (fp16 out); p = silu(u) * (hn @ w3.T) (fp16 out)
    gemm_mma<0, __half><<<dim3(HID/GBN, MB), 256, GSMEM_BYTES>>>(
        xnh, hw1, uh, DIM, HID, nullptr, nullptr, nullptr, nullptr, nullptr);
    gemm_mma<2, __half><<<dim3(HID/GBN, MB), 256, GSMEM_BYTES>>>(
        xnh, hw3, ph, DIM, HID, nullptr, nullptr, uh, nullptr, nullptr);

    // 8. out = h + (p @ w2.T) * ffn_scale  (fp32 out)
    gemm_mma<1, float><<<dim3(DIM/GBN, MB), 256, GSMEM_BYTES>>>(
        ph, hw2, out, HID, DIM, h, ffn_scale, nullptr, nullptr, nullptr);
}

// round 6
// speedup vs baseline: 6.3933x; 1.8726x over previous
#include <cuda_runtime.h>
#include <cuda_fp16.h>
#include <math.h>
#include <stdint.h>

// Problem constants
#define BB   2
#define TT   2048
#define MROWS (BB*TT)        // 4096
#define DIM  1024
#define HID  4096
#define NH   16
#define KVH  4
#define HD   64
#define WIN  512

// ---------------- scratch (device globals; no allocs allowed) ----------------
__device__ float  g_h [MROWS * DIM];      // residual 1 (fp32)
__device__ __half g_xnh[MROWS * DIM];     // rmsnorm out (xn / hn)
__device__ __half g_qh [MROWS * NH * HD];
__device__ __half g_kh [MROWS * KVH * HD];
__device__ __half g_vt [KVH * HD * MROWS];  // V transposed: [channel][token]
__device__ __half g_yh [MROWS * NH * HD]; // attention out
__device__ __half g_uh [MROWS * HID];     // w1 out (pre-activation)
__device__ __half g_ph [MROWS * HID];     // silu(u)*g
// fp16 weights
__device__ __half g_wq[NH*HD * DIM];
__device__ __half g_wk[KVH*HD * DIM];
__device__ __half g_wv[KVH*HD * DIM];
__device__ __half g_wo[DIM * NH*HD];
__device__ __half g_w1[HID * DIM];
__device__ __half g_w2[DIM * HID];
__device__ __half g_w3[HID * DIM];

// ================= helpers =================
__device__ __forceinline__ uint32_t smem_u32(const void* p) {
    uint32_t a;
    asm("{ .reg .u64 t; cvta.to.shared.u64 t, %1; cvt.u32.u64 %0, t; }" : "=r"(a) : "l"(p));
    return a;
}
__device__ __forceinline__ void cp_async16(uint32_t dst, const void* src) {
    asm volatile("cp.async.cg.shared.global [%0], [%1], 16;" :: "r"(dst), "l"(src) : "memory");
}
__device__ __forceinline__ void cp_commit() {
    asm volatile("cp.async.commit_group;" ::: "memory");
}
__device__ __forceinline__ void cp_wait1() {
    asm volatile("cp.async.wait_group 1;" ::: "memory");
}
__device__ __forceinline__ void cp_wait0() {
    asm volatile("cp.async.wait_group 0;" ::: "memory");
}
__device__ __forceinline__ void mma_f16(float* d, const uint32_t* a, const uint32_t* b) {
    asm volatile(
        "mma.sync.aligned.m16n8k16.row.col.f32.f16.f16.f32 "
        "{%0,%1,%2,%3}, {%4,%5,%6,%7}, {%8,%9}, {%0,%1,%2,%3};"
        : "+f"(d[0]), "+f"(d[1]), "+f"(d[2]), "+f"(d[3])
        : "r"(a[0]), "r"(a[1]), "r"(a[2]), "r"(a[3]), "r"(b[0]), "r"(b[1]));
}

// ---------------- fused fp32 -> fp16 convert (all 7 weights) ----------------
struct F2HDescs {
    const float4* s[7];
    __half2* d[7];
    int n4[7];
};
__global__ void f2h_all(F2HDescs dd) {
    int i = blockIdx.x * 256 + threadIdx.x;
    #pragma unroll
    for (int j = 0; j < 7; j++) {
        if (i < dd.n4[j]) {
            float4 v = dd.s[j][i];
            dd.d[j][2*i]   = __floats2half2_rn(v.x, v.y);
            dd.d[j][2*i+1] = __floats2half2_rn(v.z, v.w);
            return;
        }
        i -= dd.n4[j];
    }
}

// ================= fp16 mma.sync GEMM =================
// C[M,N] = A[M,K] @ W[N,K]^T, fp16 in, fp32 accum. BM=128,BN=128,BK=32 halfs.
// 2-stage cp.async, 2 CTAs/SM. 8 warps: wm=wid&1 (64 rows), wn=wid>>1 (32 cols).
// EPI: 0 plain store; 1 C=res+acc*scale[col] (float); 2 C=silu(upre)*acc (half);
//      3 dual KV: blocks 0,1 -> K normal half; blocks 2,3 -> V transposed into C2
#define GBM 128
#define GBN 128
#define GBK 32
#define HSTRIDE 40
#define TILE_HALFS (GBM*HSTRIDE)        // 5120
#define STAGE_HALFS (2*TILE_HALFS)      // 10240
#define STAGE_BYTES (STAGE_HALFS*2)     // 20480
#define GSMEM_BYTES (2*STAGE_BYTES)     // 40960

template<int EPI, typename TO>
__global__ void __launch_bounds__(256, 2)
gemm_mma(const __half* __restrict__ A, const __half* __restrict__ W,
         TO* __restrict__ C, int K, int N,
         const float* __restrict__ res, const float* __restrict__ scale,
         const __half* __restrict__ upre,
         const __half* __restrict__ W2, __half* __restrict__ C2) {
    extern __shared__ __half sm[];
    const uint32_t sb = smem_u32(sm);
    const int tid = threadIdx.x;
    const int wid = tid >> 5, lane = tid & 31;
    const int wm = wid & 1, wn = wid >> 1;
    const int lr = lane >> 2, lc = lane & 3;

    const __half* Wp = W;
    TO* Cp = C;
    bool second = false;
    int bcol0;
    if (W2 != nullptr) {
        if (blockIdx.x >> 1) { Wp = W2; second = true; }
        bcol0 = (blockIdx.x & 1) * GBN;
    } else {
        bcol0 = blockIdx.x * GBN;
    }
    const int brow0 = blockIdx.y * GBM;

    uint32_t aoff[2], boff[2];
    const __half* ag[2];
    const __half* bg[2];
    #pragma unroll
    for (int j = 0; j < 2; j++) {
        int f = tid + j * 256;
        int row = f >> 2, kc = (f & 3) * 8;
        aoff[j] = (uint32_t)(row * HSTRIDE + kc) * 2u;
        boff[j] = aoff[j] + TILE_HALFS * 2u;
        ag[j] = A  + (size_t)(brow0 + row) * K + kc;
        bg[j] = Wp + (size_t)(bcol0 + row) * K + kc;
    }

    const int NC = K / GBK;

    #pragma unroll
    for (int s = 0; s < 2; s++) {
        uint32_t so = sb + s * STAGE_BYTES;
        int k0 = s * GBK;
        #pragma unroll
        for (int j = 0; j < 2; j++) cp_async16(so + aoff[j], ag[j] + k0);
        #pragma unroll
        for (int j = 0; j < 2; j++) cp_async16(so + boff[j], bg[j] + k0);
        cp_commit();
    }

    float acc[4][4][4];
    #pragma unroll
    for (int mt = 0; mt < 4; mt++)
        #pragma unroll
        for (int nt = 0; nt < 4; nt++)
            #pragma unroll
            for (int r = 0; r < 4; r++) acc[mt][nt][r] = 0.f;

    for (int i = 0; i < NC; i++) {
        cp_wait1();
        __syncthreads();
        const int p = i & 1;
        const __half* As = sm + p * STAGE_HALFS;
        const __half* Bs = As + TILE_HALFS;
        const __half* Aw = As + (wm * 64 + lr) * HSTRIDE + lc * 2;
        const __half* Bw = Bs + (wn * 32 + lr) * HSTRIDE + lc * 2;
        #pragma unroll
        for (int ks = 0; ks < 2; ks++) {
            uint32_t a[4][4], b[4][2];
            #pragma unroll
            for (int mt = 0; mt < 4; mt++) {
                const __half* pa = Aw + mt * 16 * HSTRIDE + ks * 16;
                a[mt][0] = *reinterpret_cast<const uint32_t*>(pa);
                a[mt][1] = *reinterpret_cast<const uint32_t*>(pa + 8 * HSTRIDE);
                a[mt][2] = *reinterpret_cast<const uint32_t*>(pa + 8);
                a[mt][3] = *reinterpret_cast<const uint32_t*>(pa + 8 * HSTRIDE + 8);
            }
            #pragma unroll
            for (int nt = 0; nt < 4; nt++) {
                const __half* pb = Bw + nt * 8 * HSTRIDE + ks * 16;
                b[nt][0] = *reinterpret_cast<const uint32_t*>(pb);
                b[nt][1] = *reinterpret_cast<const uint32_t*>(pb + 8);
            }
            #pragma unroll
            for (int mt = 0; mt < 4; mt++)
                #pragma unroll
                for (int nt = 0; nt < 4; nt++)
                    mma_f16(acc[mt][nt], a[mt], b[nt]);
        }
        __syncthreads();
        if (i + 2 < NC) {
            uint32_t so = sb + p * STAGE_BYTES;
            int k0 = (i + 2) * GBK;
            #pragma unroll
            for (int j = 0; j < 2; j++) cp_async16(so + aoff[j], ag[j] + k0);
            #pragma unroll
            for (int j = 0; j < 2; j++) cp_async16(so + boff[j], bg[j] + k0);
        }
        cp_commit();
    }

    #pragma unroll
    for (int mt = 0; mt < 4; mt++) {
        #pragma unroll
        for (int half = 0; half < 2; half++) {
            int row = brow0 + wm * 64 + mt * 16 + half * 8 + lr;
            TO* crow = Cp + (size_t)row * N;
            #pragma unroll
            for (int nt = 0; nt < 4; nt++) {
                int col = bcol0 + wn * 32 + nt * 8 + lc * 2;
                float d0 = acc[mt][nt][half * 2 + 0];
                float d1 = acc[mt][nt][half * 2 + 1];
                if (EPI == 0) {
                    if (sizeof(TO) == 2) {
                        *reinterpret_cast<__half2*>((__half*)crow + col) = __floats2half2_rn(d0, d1);
                    } else {
                        *reinterpret_cast<float2*>((float*)crow + col) = make_float2(d0, d1);
                    }
                } else if (EPI == 1) {
                    float o0 = res[(size_t)row * N + col]     + d0 * scale[col];
                    float o1 = res[(size_t)row * N + col + 1] + d1 * scale[col + 1];
                    *reinterpret_cast<float2*>((float*)crow + col) = make_float2(o0, o1);
                } else if (EPI == 2) {
                    float u0 = __half2float(upre[(size_t)row * N + col]);
                    float u1 = __half2float(upre[(size_t)row * N + col + 1]);
                    float s0 = u0 / (1.0f + __expf(-u0));
                    float s1 = u1 / (1.0f + __expf(-u1));
                    *reinterpret_cast<__half2*>((__half*)crow + col) = __floats2half2_rn(s0 * d0, s1 * d1);
                } else {  // EPI == 3
                    if (!second) {
                        *reinterpret_cast<__half2*>((__half*)crow + col) = __floats2half2_rn(d0, d1);
                    } else {
                        C2[(size_t)col * MROWS + row]       = __float2half_rn(d0);
                        C2[(size_t)(col + 1) * MROWS + row] = __float2half_rn(d1);
                    }
                }
            }
        }
    }
}

// ---------------- row RMSNorm over DIM=1024 (fp32 in, fp16 out) ----------------
__global__ void rmsnorm_kernel(const float* __restrict__ x,
                               const float* __restrict__ w,
                               __half* __restrict__ out, float eps) {
    int row = blockIdx.x;
    int tid = threadIdx.x;
    const float4* xr = reinterpret_cast<const float4*>(x + (size_t)row * DIM);
    float4 v = xr[tid];
    float ss = v.x*v.x + v.y*v.y + v.z*v.z + v.w*v.w;
    #pragma unroll
    for (int o = 16; o; o >>= 1) ss += __shfl_xor_sync(0xffffffffu, ss, o);
    __shared__ float red[8];
    __shared__ float stot;
    int lane = tid & 31, wid = tid >> 5;
    if (lane == 0) red[wid] = ss;
    __syncthreads();
    if (tid == 0) {
        float s = 0.f;
        #pragma unroll
        for (int i = 0; i < 8; i++) s += red[i];
        stot = rsqrtf(s * (1.0f / DIM) + eps);
    }
    __syncthreads();
    float sc = stot;
    const float4* wr = reinterpret_cast<const float4*>(w);
    float4 wv = wr[tid];
    __half2 h0 = __floats2half2_rn(v.x*sc*wv.x, v.y*sc*wv.y);
    __half2 h1 = __floats2half2_rn(v.z*sc*wv.z, v.w*sc*wv.w);
    __half2* op = reinterpret_cast<__half2*>(out + (size_t)row * DIM) + tid * 2;
    op[0] = h0; op[1] = h1;
}

// ---------------- per-head RMSNorm over HD=64 (fp16 in-place) ----------------
// post: extra factor folded into output (0.125 for q, 1.0 for k)
__global__ void headnorm_h(__half* __restrict__ buf, const float* __restrict__ w,
                           float post) {
    int warp = threadIdx.x >> 5;
    int lane = threadIdx.x & 31;
    size_t r = (size_t)blockIdx.x * 8 + warp;
    __half2* p = reinterpret_cast<__half2*>(buf + r * HD) + lane;
    float2 v = __half22float2(*p);
    float ss = v.x*v.x + v.y*v.y;
    #pragma unroll
    for (int o = 16; o; o >>= 1) ss += __shfl_xor_sync(0xffffffffu, ss, o);
    float sc = rsqrtf(ss * (1.0f / HD) + 1e-6f) * post;
    *p = __floats2half2_rn(v.x * sc * w[2*lane], v.y * sc * w[2*lane+1]);
}

// ---------------- fp16 mma flash attention ----------------
// grid (TT/64, NH, BB), 128 threads (4 warps, 16 q-rows each).
// q fp16 already head-normed and pre-scaled by 1/sqrt(HD).
// k fp16 head-normed. vt fp16 transposed [channel][token].
#define AST 72                       // smem row stride in halfs
#define A_QOFF 0                     // 64*72 halfs
#define A_K0 (64*AST)                // stage s: K at A_K0 + s*2*64*AST
#define A_STG (2*64*AST)
#define ASMEM_HALFS (64*AST + 2*2*64*AST)  // Q + 2 stages * (K,Vt)
#define ASMEM_BYTES (ASMEM_HALFS*2)        // 46080

__global__ void __launch_bounds__(128, 3)
attn_mma(const __half* __restrict__ q, const __half* __restrict__ k,
         const __half* __restrict__ vt, __half* __restrict__ y) {
    extern __shared__ __half asmem[];
    const uint32_t sb = smem_u32(asmem);
    const int m   = blockIdx.x;          // q tile (64 rows) within batch
    const int h   = blockIdx.y;
    const int b   = blockIdx.z;
    const int kvh = h >> 2;
    const int tid = threadIdx.x;
    const int w   = tid >> 5, lane = tid & 31;
    const int lr  = lane >> 2, lc = lane & 3;
    const int tok0 = b * TT;             // batch base token

    const int tlo = (m >= 8) ? m - 8 : 0;

    // ---- prologue: stage Q and KV(tlo) ----
    {
        // Q: 64 rows x 8 chunks (16B); 512 chunks / 128 threads = 4 each
        #pragma unroll
        for (int i = 0; i < 4; i++) {
            int c = tid + i * 128;
            int row = c >> 3, cc = c & 7;
            cp_async16(sb + (uint32_t)(row * AST + cc * 8) * 2,
                       q + (size_t)(tok0 + m * 64 + row) * (NH * HD) + h * HD + cc * 8);
        }
        // K(tlo), Vt(tlo) into stage 0
        #pragma unroll
        for (int i = 0; i < 4; i++) {
            int c = tid + i * 128;
            int row = c >> 3, cc = c & 7;
            cp_async16(sb + (uint32_t)(A_K0 + row * AST + cc * 8) * 2,
                       k + (size_t)(tok0 + tlo * 64 + row) * (KVH * HD) + kvh * HD + cc * 8);
            cp_async16(sb + (uint32_t)(A_K0 + 64 * AST + row * AST + cc * 8) * 2,
                       vt + (size_t)(kvh * HD + row) * MROWS + tok0 + tlo * 64 + cc * 8);
        }
        cp_commit();
    }

    uint32_t qf[4][4];
    float acco[8][4];
    #pragma unroll
    for (int nt = 0; nt < 8; nt++)
        #pragma unroll
        for (int r = 0; r < 4; r++) acco[nt][r] = 0.f;
    float mx0 = -INFINITY, mx1 = -INFINITY, l0 = 0.f, l1 = 0.f;

    const int r0 = m * 64 + w * 16 + lr;   // within-batch query row
    const int r1 = r0 + 8;

    for (int t = tlo; t <= m; t++) {
        const int s = (t - tlo) & 1;
        // prefetch next tile into other stage
        if (t < m) {
            const int sn = s ^ 1;
            #pragma unroll
            for (int i = 0; i < 4; i++) {
                int c = tid + i * 128;
                int row = c >> 3, cc = c & 7;
                cp_async16(sb + (uint32_t)(A_K0 + sn * A_STG + row * AST + cc * 8) * 2,
                           k + (size_t)(tok0 + (t+1) * 64 + row) * (KVH * HD) + kvh * HD + cc * 8);
                cp_async16(sb + (uint32_t)(A_K0 + sn * A_STG + 64 * AST + row * AST + cc * 8) * 2,
                           vt + (size_t)(kvh * HD + row) * MROWS + tok0 + (t+1) * 64 + cc * 8);
            }
        }
        cp_commit();
        if (t < m) cp_wait1(); else cp_wait0();
        __syncthreads();

        if (t == tlo) {
            // load Q fragments once
            const __half* Aw = asmem + (w * 16 + lr) * AST + lc * 2;
            #pragma unroll
            for (int ks = 0; ks < 4; ks++) {
                const __half* pa = Aw + ks * 16;
                qf[ks][0] = *reinterpret_cast<const uint32_t*>(pa);
                qf[ks][1] = *reinterpret_cast<const uint32_t*>(pa + 8 * AST);
                qf[ks][2] = *reinterpret_cast<const uint32_t*>(pa + 8);
                qf[ks][3] = *reinterpret_cast<const uint32_t*>(pa + 8 * AST + 8);
            }
        }

        const __half* Ks = asmem + A_K0 + s * A_STG;
        const __half* Vs = Ks + 64 * AST;

        // S = Q @ K^T
        float accs[8][4];
        #pragma unroll
        for (int nt = 0; nt < 8; nt++)
            #pragma unroll
            for (int r = 0; r < 4; r++) accs[nt][r] = 0.f;
        #pragma unroll
        for (int nt = 0; nt < 8; nt++) {
            const __half* pbb = Ks + (nt * 8 + lr) * AST + lc * 2;
            #pragma unroll
            for (int ks = 0; ks < 4; ks++) {
                uint32_t bb[2];
                bb[0] = *reinterpret_cast<const uint32_t*>(pbb + ks * 16);
                bb[1] = *reinterpret_cast<const uint32_t*>(pbb + ks * 16 + 8);
                mma_f16(accs[nt], qf[ks], bb);
            }
        }

        // mask (diag tile and window-edge tile)
        if (t == m || t + 8 == m) {
            #pragma unroll
            for (int nt = 0; nt < 8; nt++) {
                int c0 = t * 64 + nt * 8 + lc * 2;
                #pragma unroll
                for (int r = 0; r < 4; r++) {
                    int row = (r < 2) ? r0 : r1;
                    int col = c0 + (r & 1);
                    bool valid = (col <= row) && (col + WIN > row);
                    if (!valid) accs[nt][r] = -1e30f;
                }
            }
        }

        // online softmax (rows r0: regs 0,1; r1: regs 2,3)
        float tm0 = -1e30f, tm1 = -1e30f;
        #pragma unroll
        for (int nt = 0; nt < 8; nt++) {
            tm0 = fmaxf(tm0, fmaxf(accs[nt][0], accs[nt][1]));
            tm1 = fmaxf(tm1, fmaxf(accs[nt][2], accs[nt][3]));
        }
        tm0 = fmaxf(tm0, __shfl_xor_sync(0xffffffffu, tm0, 1));
        tm0 = fmaxf(tm0, __shfl_xor_sync(0xffffffffu, tm0, 2));
        tm1 = fmaxf(tm1, __shfl_xor_sync(0xffffffffu, tm1, 1));
        tm1 = fmaxf(tm1, __shfl_xor_sync(0xffffffffu, tm1, 2));
        float nm0 = fmaxf(mx0, tm0), nm1 = fmaxf(mx1, tm1);
        float corr0 = __expf(mx0 - nm0), corr1 = __expf(mx1 - nm1);
        mx0 = nm0; mx1 = nm1;

        float sum0 = 0.f, sum1 = 0.f;
        #pragma unroll
        for (int nt = 0; nt < 8; nt++) {
            accs[nt][0] = __expf(accs[nt][0] - nm0);
            accs[nt][1] = __expf(accs[nt][1] - nm0);
            accs[nt][2] = __expf(accs[nt][2] - nm1);
            accs[nt][3] = __expf(accs[nt][3] - nm1);
            sum0 += accs[nt][0] + accs[nt][1];
            sum1 += accs[nt][2] + accs[nt][3];
        }
        sum0 += __shfl_xor_sync(0xffffffffu, sum0, 1);
        sum0 += __shfl_xor_sync(0xffffffffu, sum0, 2);
        sum1 += __shfl_xor_sync(0xffffffffu, sum1, 1);
        sum1 += __shfl_xor_sync(0xffffffffu, sum1, 2);
        l0 = l0 * corr0 + sum0;
        l1 = l1 * corr1 + sum1;
        #pragma unroll
        for (int nt = 0; nt < 8; nt++) {
            acco[nt][0] *= corr0; acco[nt][1] *= corr0;
            acco[nt][2] *= corr1; acco[nt][3] *= corr1;
        }

        // P fragments (fp16) from S tiles: ks-th slice = tiles 2ks, 2ks+1
        uint32_t pf[4][4];
        #pragma unroll
        for (int ks = 0; ks < 4; ks++) {
            __half2 h0 = __floats2half2_rn(accs[2*ks][0],   accs[2*ks][1]);
            __half2 h1 = __floats2half2_rn(accs[2*ks][2],   accs[2*ks][3]);
            __half2 h2 = __floats2half2_rn(accs[2*ks+1][0], accs[2*ks+1][1]);
            __half2 h3 = __floats2half2_rn(accs[2*ks+1][2], accs[2*ks+1][3]);
            pf[ks][0] = *reinterpret_cast<uint32_t*>(&h0);
            pf[ks][1] = *reinterpret_cast<uint32_t*>(&h1);
            pf[ks][2] = *reinterpret_cast<uint32_t*>(&h2);
            pf[ks][3] = *reinterpret_cast<uint32_t*>(&h3);
        }

        // O += P @ V
        #pragma unroll
        for (int nt = 0; nt < 8; nt++) {
            const __half* pbb = Vs + (nt * 8 + lr) * AST + lc * 2;
            #pragma unroll
            for (int ks = 0; ks < 4; ks++) {
                uint32_t bb[2];
                bb[0] = *reinterpret_cast<const uint32_t*>(pbb + ks * 16);
                bb[1] = *reinterpret_cast<const uint32_t*>(pbb + ks * 16 + 8);
                mma_f16(acco[nt], pf[ks], bb);
            }
        }
        __syncthreads();
    }

    float inv0 = 1.0f / l0, inv1 = 1.0f / l1;
    __half* y0 = y + (size_t)(tok0 + r0) * (NH * HD) + h * HD;
    __half* y1 = y + (size_t)(tok0 + r1) * (NH * HD) + h * HD;
    #pragma unroll
    for (int nt = 0; nt < 8; nt++) {
        int col = nt * 8 + lc * 2;
        *reinterpret_cast<__half2*>(y0 + col) = __floats2half2_rn(acco[nt][0]*inv0, acco[nt][1]*inv0);
        *reinterpret_cast<__half2*>(y1 + col) = __floats2half2_rn(acco[nt][2]*inv1, acco[nt][3]*inv1);
    }
}

// ---------------- launch ----------------
extern "C" void kernel_launch(void* const* d_in, const int* in_sizes, int n_in,
                              void* d_out, int out_size) {
    const float* x          = (const float*)d_in[0];
    const float* wq         = (const float*)d_in[1];
    const float* wk         = (const float*)d_in[2];
    const float* wv         = (const float*)d_in[3];
    const float* wo         = (const float*)d_in[4];
    const float* w1         = (const float*)d_in[5];
    const float* w2         = (const float*)d_in[6];
    const float* w3         = (const float*)d_in[7];
    const float* q_norm_w   = (const float*)d_in[8];
    const float* k_norm_w   = (const float*)d_in[9];
    const float* attn_norm_w= (const float*)d_in[10];
    const float* ffn_norm_w = (const float*)d_in[11];
    const float* attn_scale = (const float*)d_in[12];
    const float* ffn_scale  = (const float*)d_in[13];
    float* out = (float*)d_out;

    float* h;
    __half *xnh, *qh, *kh, *vth, *yh, *uh, *ph;
    __half *hwq, *hwk, *hwv, *hwo, *hw1, *hw2, *hw3;
    cudaGetSymbolAddress((void**)&h,   g_h);
    cudaGetSymbolAddress((void**)&xnh, g_xnh);
    cudaGetSymbolAddress((void**)&qh,  g_qh);
    cudaGetSymbolAddress((void**)&kh,  g_kh);
    cudaGetSymbolAddress((void**)&vth, g_vt);
    cudaGetSymbolAddress((void**)&yh,  g_yh);
    cudaGetSymbolAddress((void**)&uh,  g_uh);
    cudaGetSymbolAddress((void**)&ph,  g_ph);
    cudaGetSymbolAddress((void**)&hwq, g_wq);
    cudaGetSymbolAddress((void**)&hwk, g_wk);
    cudaGetSymbolAddress((void**)&hwv, g_wv);
    cudaGetSymbolAddress((void**)&hwo, g_wo);
    cudaGetSymbolAddress((void**)&hw1, g_w1);
    cudaGetSymbolAddress((void**)&hw2, g_w2);
    cudaGetSymbolAddress((void**)&hw3, g_w3);

    static bool attr_done = false;
    if (!attr_done) {
        cudaFuncSetAttribute((const void*)gemm_mma<0, float>,  cudaFuncAttributeMaxDynamicSharedMemorySize, GSMEM_BYTES);
        cudaFuncSetAttribute((const void*)gemm_mma<0, __half>, cudaFuncAttributeMaxDynamicSharedMemorySize, GSMEM_BYTES);
        cudaFuncSetAttribute((const void*)gemm_mma<1, float>,  cudaFuncAttributeMaxDynamicSharedMemorySize, GSMEM_BYTES);
        cudaFuncSetAttribute((const void*)gemm_mma<2, __half>, cudaFuncAttributeMaxDynamicSharedMemorySize, GSMEM_BYTES);
        cudaFuncSetAttribute((const void*)gemm_mma<3, __half>, cudaFuncAttributeMaxDynamicSharedMemorySize, GSMEM_BYTES);
        cudaFuncSetAttribute((const void*)attn_mma, cudaFuncAttributeMaxDynamicSharedMemorySize, ASMEM_BYTES);
        attr_done = true;
    }

    // 0. convert weights fp32 -> fp16 (single fused kernel)
    {
        F2HDescs dd;
        const float* srcs[7] = {wq, wk, wv, wo, w1, w2, w3};
        __half* dsts[7] = {hwq, hwk, hwv, hwo, hw1, hw2, hw3};
        int ns[7] = {NH*HD*DIM/4, KVH*HD*DIM/4, KVH*HD*DIM/4, DIM*NH*HD/4,
                     HID*DIM/4, DIM*HID/4, HID*DIM/4};
        int total = 0;
        for (int j = 0; j < 7; j++) {
            dd.s[j] = (const float4*)srcs[j];
            dd.d[j] = (__half2*)dsts[j];
            dd.n4[j] = ns[j];
            total += ns[j];
        }
        f2h_all<<<(total + 255) / 256, 256>>>(dd);
    }

    const int MB = MROWS / GBM;   // 32

    // 1. xn = rmsnorm(x, attn_norm_w) -> fp16
    rmsnorm_kernel<<<MROWS, 256>>>(x, attn_norm_w, xnh, 1e-5f);

    // 2. q projection (fp16 out); k normal + v transposed dual launch
    gemm_mma<0, __half><<<dim3(DIM/GBN, MB), 256, GSMEM_BYTES>>>(
        xnh, hwq, qh, DIM, DIM, nullptr, nullptr, nullptr, nullptr, nullptr);
    gemm_mma<3, __half><<<dim3(4, MB), 256, GSMEM_BYTES>>>(
        xnh, hwk, kh, DIM, KVH*HD, nullptr, nullptr, nullptr, hwv, vth);

    // 3. head rmsnorm: q (x0.125 folded), k
    headnorm_h<<<(MROWS * NH) / 8, 256>>>(qh, q_norm_w, 0.125f);
    headnorm_h<<<(MROWS * KVH) / 8, 256>>>(kh, k_norm_w, 1.0f);

    // 4. flash attention (fp16 mma)
    attn_mma<<<dim3(TT/64, NH, BB), 128, ASMEM_BYTES>>>(qh, kh, vth, yh);

    // 5. h = x + (y @ wo.T) * attn_scale   (fp32 out)
    gemm_mma<1, float><<<dim3(DIM/GBN, MB), 256, GSMEM_BYTES>>>(
        yh, hwo, h, DIM, DIM, x, attn_scale, nullptr, nullptr, nullptr);

    // 6. hn = rmsnorm(h, ffn_norm_w) -> fp16
    rmsnorm_kernel<<<MROWS, 256>>>(h, ffn_norm_w, xnh, 1e-5f);

    // 7. u = hn @ w1.T (fp16); p = silu(u) * (hn @ w3.T) (fp16)
    gemm_mma<0, __half><<<dim3(HID/GBN, MB), 256, GSMEM_BYTES>>>(
        xnh, hw1, uh, DIM, HID, nullptr, nullptr, nullptr, nullptr, nullptr);
    gemm_mma<2, __half><<<dim3(HID/GBN, MB), 256, GSMEM_BYTES>>>(
        xnh, hw3, ph, DIM, HID, nullptr, nullptr, uh, nullptr, nullptr);

    // 8. out = h + (p @ w2.T) * ffn_scale  (fp32 out)
    gemm_mma<1, float><<<dim3(DIM/GBN, MB), 256, GSMEM_BYTES>>>(
        ph, hw2, out, HID, DIM, h, ffn_scale, nullptr, nullptr, nullptr);
}

// round 7
// speedup vs baseline: 6.8864x; 1.0771x over previous
#include <cuda_runtime.h>
#include <cuda_fp16.h>
#include <math.h>
#include <stdint.h>

// Problem constants
#define BB   2
#define TT   2048
#define MROWS (BB*TT)        // 4096
#define DIM  1024
#define HID  4096
#define NH   16
#define KVH  4
#define HD   64
#define WIN  512

// ---------------- scratch (device globals; no allocs allowed) ----------------
__device__ float  g_h [MROWS * DIM];      // residual 1 (fp32)
__device__ __half g_xnh[MROWS * DIM];     // rmsnorm out (xn / hn)
__device__ __half g_qh [MROWS * NH * HD];
__device__ __half g_kh [MROWS * KVH * HD];
__device__ __half g_vt [KVH * HD * MROWS];  // V transposed: [channel][token]
__device__ __half g_yh [MROWS * NH * HD]; // attention out
__device__ __half g_uh [MROWS * HID];     // w1 out (pre-activation)
__device__ __half g_ph [MROWS * HID];     // silu(u)*g
// fp16 weights
__device__ __half g_wq[NH*HD * DIM];
__device__ __half g_wk[KVH*HD * DIM];
__device__ __half g_wv[KVH*HD * DIM];
__device__ __half g_wo[DIM * NH*HD];
__device__ __half g_w1[HID * DIM];
__device__ __half g_w2[DIM * HID];
__device__ __half g_w3[HID * DIM];

// ================= helpers =================
__device__ __forceinline__ uint32_t smem_u32(const void* p) {
    uint32_t a;
    asm("{ .reg .u64 t; cvta.to.shared.u64 t, %1; cvt.u32.u64 %0, t; }" : "=r"(a) : "l"(p));
    return a;
}
__device__ __forceinline__ void cp_async16(uint32_t dst, const void* src) {
    asm volatile("cp.async.cg.shared.global [%0], [%1], 16;" :: "r"(dst), "l"(src) : "memory");
}
__device__ __forceinline__ void cp_commit() {
    asm volatile("cp.async.commit_group;" ::: "memory");
}
__device__ __forceinline__ void cp_wait2() {
    asm volatile("cp.async.wait_group 2;" ::: "memory");
}
__device__ __forceinline__ void cp_wait1() {
    asm volatile("cp.async.wait_group 1;" ::: "memory");
}
__device__ __forceinline__ void cp_wait0() {
    asm volatile("cp.async.wait_group 0;" ::: "memory");
}
__device__ __forceinline__ void mma_f16(float* d, const uint32_t* a, const uint32_t* b) {
    asm volatile(
        "mma.sync.aligned.m16n8k16.row.col.f32.f16.f16.f32 "
        "{%0,%1,%2,%3}, {%4,%5,%6,%7}, {%8,%9}, {%0,%1,%2,%3};"
        : "+f"(d[0]), "+f"(d[1]), "+f"(d[2]), "+f"(d[3])
        : "r"(a[0]), "r"(a[1]), "r"(a[2]), "r"(a[3]), "r"(b[0]), "r"(b[1]));
}
__device__ __forceinline__ void ldsm_x4(uint32_t* r, uint32_t addr) {
    asm volatile("ldmatrix.sync.aligned.m8n8.x4.shared.b16 {%0,%1,%2,%3}, [%4];"
                 : "=r"(r[0]), "=r"(r[1]), "=r"(r[2]), "=r"(r[3]) : "r"(addr));
}

// ---------------- fused fp32 -> fp16 convert (all 7 weights) ----------------
struct F2HDescs {
    const float4* s[7];
    __half2* d[7];
    int n4[7];
};
__global__ void f2h_all(F2HDescs dd) {
    int i = blockIdx.x * 256 + threadIdx.x;
    #pragma unroll
    for (int j = 0; j < 7; j++) {
        if (i < dd.n4[j]) {
            float4 v = dd.s[j][i];
            dd.d[j][2*i]   = __floats2half2_rn(v.x, v.y);
            dd.d[j][2*i+1] = __floats2half2_rn(v.z, v.w);
            return;
        }
        i -= dd.n4[j];
    }
}

// ================= fp16 mma.sync GEMM (ldmatrix, 3-stage) =================
// C[M,N] = A[M,K] @ W[N,K]^T. BM=128,BN=128,BK=32. 2 CTAs/SM.
// EPI: 0 plain; 1 res+acc*scale (float); 2 silu(upre)*acc (half);
//      3 dual KV: blocks 0,1 -> K half; blocks 2,3 -> V transposed into C2
#define GBM 128
#define GBN 128
#define GBK 32
#define HSTRIDE 40
#define TILE_HALFS (GBM*HSTRIDE)        // 5120
#define STAGE_HALFS (2*TILE_HALFS)      // 10240
#define STAGE_BYTES (STAGE_HALFS*2)     // 20480
#define GSTAGES 3
#define GSMEM_BYTES (GSTAGES*STAGE_BYTES)  // 61440

template<int EPI, typename TO>
__global__ void __launch_bounds__(256, 2)
gemm_mma(const __half* __restrict__ A, const __half* __restrict__ W,
         TO* __restrict__ C, int K, int N,
         const float* __restrict__ res, const float* __restrict__ scale,
         const __half* __restrict__ upre,
         const __half* __restrict__ W2, __half* __restrict__ C2) {
    extern __shared__ __half sm[];
    const uint32_t sb = smem_u32(sm);
    const int tid = threadIdx.x;
    const int wid = tid >> 5, lane = tid & 31;
    const int wm = wid & 1, wn = wid >> 1;
    const int lr = lane >> 2, lc = lane & 3;

    const __half* Wp = W;
    TO* Cp = C;
    bool second = false;
    int bcol0;
    if (W2 != nullptr) {
        if (blockIdx.x >> 1) { Wp = W2; second = true; }
        bcol0 = (blockIdx.x & 1) * GBN;
    } else {
        bcol0 = blockIdx.x * GBN;
    }
    const int brow0 = blockIdx.y * GBM;

    uint32_t aoff[2], boff[2];
    const __half* ag[2];
    const __half* bg[2];
    #pragma unroll
    for (int j = 0; j < 2; j++) {
        int f = tid + j * 256;
        int row = f >> 2, kc = (f & 3) * 8;
        aoff[j] = (uint32_t)(row * HSTRIDE + kc) * 2u;
        boff[j] = aoff[j] + TILE_HALFS * 2u;
        ag[j] = A  + (size_t)(brow0 + row) * K + kc;
        bg[j] = Wp + (size_t)(bcol0 + row) * K + kc;
    }

    // ldmatrix per-thread base offsets (within a stage), in bytes
    const uint32_t a_lm = (uint32_t)((wm * 64 + (lane & 15)) * HSTRIDE + ((lane >> 4) << 3)) * 2u;
    const uint32_t b_lm = (uint32_t)(TILE_HALFS +
                         (wn * 32 + (lane & 7) + ((lane >> 4) << 3)) * HSTRIDE +
                         (((lane >> 3) & 1) << 3)) * 2u;

    const int NC = K / GBK;

    #pragma unroll
    for (int s = 0; s < GSTAGES; s++) {
        uint32_t so = sb + s * STAGE_BYTES;
        int k0 = s * GBK;
        #pragma unroll
        for (int j = 0; j < 2; j++) cp_async16(so + aoff[j], ag[j] + k0);
        #pragma unroll
        for (int j = 0; j < 2; j++) cp_async16(so + boff[j], bg[j] + k0);
        cp_commit();
    }

    float acc[4][4][4];
    #pragma unroll
    for (int mt = 0; mt < 4; mt++)
        #pragma unroll
        for (int nt = 0; nt < 4; nt++)
            #pragma unroll
            for (int r = 0; r < 4; r++) acc[mt][nt][r] = 0.f;

    for (int i = 0; i < NC; i++) {
        cp_wait2();
        __syncthreads();
        const int p = i % GSTAGES;
        const uint32_t sA = sb + p * STAGE_BYTES + a_lm;
        const uint32_t sB = sb + p * STAGE_BYTES + b_lm;
        #pragma unroll
        for (int ks = 0; ks < 2; ks++) {
            uint32_t a[4][4], b[2][4];
            #pragma unroll
            for (int mt = 0; mt < 4; mt++)
                ldsm_x4(a[mt], sA + (uint32_t)(mt * 16 * HSTRIDE + ks * 16) * 2u);
            #pragma unroll
            for (int np = 0; np < 2; np++)
                ldsm_x4(b[np], sB + (uint32_t)(np * 16 * HSTRIDE + ks * 16) * 2u);
            #pragma unroll
            for (int mt = 0; mt < 4; mt++)
                #pragma unroll
                for (int nt = 0; nt < 4; nt++)
                    mma_f16(acc[mt][nt], a[mt], &b[nt >> 1][(nt & 1) * 2]);
        }
        __syncthreads();
        if (i + GSTAGES < NC) {
            uint32_t so = sb + p * STAGE_BYTES;
            int k0 = (i + GSTAGES) * GBK;
            #pragma unroll
            for (int j = 0; j < 2; j++) cp_async16(so + aoff[j], ag[j] + k0);
            #pragma unroll
            for (int j = 0; j < 2; j++) cp_async16(so + boff[j], bg[j] + k0);
        }
        cp_commit();
    }

    #pragma unroll
    for (int mt = 0; mt < 4; mt++) {
        #pragma unroll
        for (int half = 0; half < 2; half++) {
            int row = brow0 + wm * 64 + mt * 16 + half * 8 + lr;
            TO* crow = Cp + (size_t)row * N;
            #pragma unroll
            for (int nt = 0; nt < 4; nt++) {
                int col = bcol0 + wn * 32 + nt * 8 + lc * 2;
                float d0 = acc[mt][nt][half * 2 + 0];
                float d1 = acc[mt][nt][half * 2 + 1];
                if (EPI == 0) {
                    if (sizeof(TO) == 2) {
                        *reinterpret_cast<__half2*>((__half*)crow + col) = __floats2half2_rn(d0, d1);
                    } else {
                        *reinterpret_cast<float2*>((float*)crow + col) = make_float2(d0, d1);
                    }
                } else if (EPI == 1) {
                    float o0 = res[(size_t)row * N + col]     + d0 * scale[col];
                    float o1 = res[(size_t)row * N + col + 1] + d1 * scale[col + 1];
                    *reinterpret_cast<float2*>((float*)crow + col) = make_float2(o0, o1);
                } else if (EPI == 2) {
                    float u0 = __half2float(upre[(size_t)row * N + col]);
                    float u1 = __half2float(upre[(size_t)row * N + col + 1]);
                    float s0 = u0 / (1.0f + __expf(-u0));
                    float s1 = u1 / (1.0f + __expf(-u1));
                    *reinterpret_cast<__half2*>((__half*)crow + col) = __floats2half2_rn(s0 * d0, s1 * d1);
                } else {  // EPI == 3
                    if (!second) {
                        *reinterpret_cast<__half2*>((__half*)crow + col) = __floats2half2_rn(d0, d1);
                    } else {
                        C2[(size_t)col * MROWS + row]       = __float2half_rn(d0);
                        C2[(size_t)(col + 1) * MROWS + row] = __float2half_rn(d1);
                    }
                }
            }
        }
    }
}

// ---------------- row RMSNorm over DIM=1024 (fp32 in, fp16 out) ----------------
__global__ void rmsnorm_kernel(const float* __restrict__ x,
                               const float* __restrict__ w,
                               __half* __restrict__ out, float eps) {
    int row = blockIdx.x;
    int tid = threadIdx.x;
    const float4* xr = reinterpret_cast<const float4*>(x + (size_t)row * DIM);
    float4 v = xr[tid];
    float ss = v.x*v.x + v.y*v.y + v.z*v.z + v.w*v.w;
    #pragma unroll
    for (int o = 16; o; o >>= 1) ss += __shfl_xor_sync(0xffffffffu, ss, o);
    __shared__ float red[8];
    __shared__ float stot;
    int lane = tid & 31, wid = tid >> 5;
    if (lane == 0) red[wid] = ss;
    __syncthreads();
    if (tid == 0) {
        float s = 0.f;
        #pragma unroll
        for (int i = 0; i < 8; i++) s += red[i];
        stot = rsqrtf(s * (1.0f / DIM) + eps);
    }
    __syncthreads();
    float sc = stot;
    const float4* wr = reinterpret_cast<const float4*>(w);
    float4 wv = wr[tid];
    __half2 h0 = __floats2half2_rn(v.x*sc*wv.x, v.y*sc*wv.y);
    __half2 h1 = __floats2half2_rn(v.z*sc*wv.z, v.w*sc*wv.w);
    __half2* op = reinterpret_cast<__half2*>(out + (size_t)row * DIM) + tid * 2;
    op[0] = h0; op[1] = h1;
}

// ---------------- per-head RMSNorm over HD=64 (fp16 in-place) ----------------
__global__ void headnorm_h(__half* __restrict__ buf, const float* __restrict__ w,
                           float post) {
    int warp = threadIdx.x >> 5;
    int lane = threadIdx.x & 31;
    size_t r = (size_t)blockIdx.x * 8 + warp;
    __half2* p = reinterpret_cast<__half2*>(buf + r * HD) + lane;
    float2 v = __half22float2(*p);
    float ss = v.x*v.x + v.y*v.y;
    #pragma unroll
    for (int o = 16; o; o >>= 1) ss += __shfl_xor_sync(0xffffffffu, ss, o);
    float sc = rsqrtf(ss * (1.0f / HD) + 1e-6f) * post;
    *p = __floats2half2_rn(v.x * sc * w[2*lane], v.y * sc * w[2*lane+1]);
}

// ---------------- fp16 mma flash attention (ldmatrix) ----------------
// grid (TT/64, NH, BB), 128 threads (4 warps, 16 q-rows each).
#define AST 72
#define A_K0 (64*AST)
#define A_STG (2*64*AST)
#define ASMEM_HALFS (64*AST + 2*2*64*AST)
#define ASMEM_BYTES (ASMEM_HALFS*2)        // 46080

__global__ void __launch_bounds__(128, 3)
attn_mma(const __half* __restrict__ q, const __half* __restrict__ k,
         const __half* __restrict__ vt, __half* __restrict__ y) {
    extern __shared__ __half asmem[];
    const uint32_t sb = smem_u32(asmem);
    const int m   = blockIdx.x;
    const int h   = blockIdx.y;
    const int b   = blockIdx.z;
    const int kvh = h >> 2;
    const int tid = threadIdx.x;
    const int w   = tid >> 5, lane = tid & 31;
    const int lr  = lane >> 2, lc = lane & 3;
    const int tok0 = b * TT;

    const int tlo = (m >= 8) ? m - 8 : 0;

    // ldmatrix base offsets (bytes)
    const uint32_t q_lm = (uint32_t)((w * 16 + (lane & 15)) * AST + ((lane >> 4) << 3)) * 2u;
    const uint32_t kv_lm = (uint32_t)(((lane & 7) + ((lane >> 4) << 3)) * AST +
                                      (((lane >> 3) & 1) << 3)) * 2u;

    {
        #pragma unroll
        for (int i = 0; i < 4; i++) {
            int c = tid + i * 128;
            int row = c >> 3, cc = c & 7;
            cp_async16(sb + (uint32_t)(row * AST + cc * 8) * 2,
                       q + (size_t)(tok0 + m * 64 + row) * (NH * HD) + h * HD + cc * 8);
        }
        #pragma unroll
        for (int i = 0; i < 4; i++) {
            int c = tid + i * 128;
            int row = c >> 3, cc = c & 7;
            cp_async16(sb + (uint32_t)(A_K0 + row * AST + cc * 8) * 2,
                       k + (size_t)(tok0 + tlo * 64 + row) * (KVH * HD) + kvh * HD + cc * 8);
            cp_async16(sb + (uint32_t)(A_K0 + 64 * AST + row * AST + cc * 8) * 2,
                       vt + (size_t)(kvh * HD + row) * MROWS + tok0 + tlo * 64 + cc * 8);
        }
        cp_commit();
    }

    uint32_t qf[4][4];
    float acco[8][4];
    #pragma unroll
    for (int nt = 0; nt < 8; nt++)
        #pragma unroll
        for (int r = 0; r < 4; r++) acco[nt][r] = 0.f;
    float mx0 = -INFINITY, mx1 = -INFINITY, l0 = 0.f, l1 = 0.f;

    const int r0 = m * 64 + w * 16 + lr;
    const int r1 = r0 + 8;

    for (int t = tlo; t <= m; t++) {
        const int s = (t - tlo) & 1;
        if (t < m) {
            const int sn = s ^ 1;
            #pragma unroll
            for (int i = 0; i < 4; i++) {
                int c = tid + i * 128;
                int row = c >> 3, cc = c & 7;
                cp_async16(sb + (uint32_t)(A_K0 + sn * A_STG + row * AST + cc * 8) * 2,
                           k + (size_t)(tok0 + (t+1) * 64 + row) * (KVH * HD) + kvh * HD + cc * 8);
                cp_async16(sb + (uint32_t)(A_K0 + sn * A_STG + 64 * AST + row * AST + cc * 8) * 2,
                           vt + (size_t)(kvh * HD + row) * MROWS + tok0 + (t+1) * 64 + cc * 8);
            }
        }
        cp_commit();
        if (t < m) cp_wait1(); else cp_wait0();
        __syncthreads();

        if (t == tlo) {
            #pragma unroll
            for (int ks = 0; ks < 4; ks++)
                ldsm_x4(qf[ks], sb + q_lm + (uint32_t)(ks * 16) * 2u);
        }

        const uint32_t sK = sb + (uint32_t)(A_K0 + s * A_STG) * 2u + kv_lm;
        const uint32_t sV = sK + (uint32_t)(64 * AST) * 2u;

        // S = Q @ K^T
        float accs[8][4];
        #pragma unroll
        for (int nt = 0; nt < 8; nt++)
            #pragma unroll
            for (int r = 0; r < 4; r++) accs[nt][r] = 0.f;
        #pragma unroll
        for (int np = 0; np < 4; np++) {
            #pragma unroll
            for (int ks = 0; ks < 4; ks++) {
                uint32_t bfr[4];
                ldsm_x4(bfr, sK + (uint32_t)(np * 16 * AST + ks * 16) * 2u);
                mma_f16(accs[2*np],   qf[ks], &bfr[0]);
                mma_f16(accs[2*np+1], qf[ks], &bfr[2]);
            }
        }

        if (t == m || t + 8 == m) {
            #pragma unroll
            for (int nt = 0; nt < 8; nt++) {
                int c0 = t * 64 + nt * 8 + lc * 2;
                #pragma unroll
                for (int r = 0; r < 4; r++) {
                    int row = (r < 2) ? r0 : r1;
                    int col = c0 + (r & 1);
                    bool valid = (col <= row) && (col + WIN > row);
                    if (!valid) accs[nt][r] = -1e30f;
                }
            }
        }

        float tm0 = -1e30f, tm1 = -1e30f;
        #pragma unroll
        for (int nt = 0; nt < 8; nt++) {
            tm0 = fmaxf(tm0, fmaxf(accs[nt][0], accs[nt][1]));
            tm1 = fmaxf(tm1, fmaxf(accs[nt][2], accs[nt][3]));
        }
        tm0 = fmaxf(tm0, __shfl_xor_sync(0xffffffffu, tm0, 1));
        tm0 = fmaxf(tm0, __shfl_xor_sync(0xffffffffu, tm0, 2));
        tm1 = fmaxf(tm1, __shfl_xor_sync(0xffffffffu, tm1, 1));
        tm1 = fmaxf(tm1, __shfl_xor_sync(0xffffffffu, tm1, 2));
        float nm0 = fmaxf(mx0, tm0), nm1 = fmaxf(mx1, tm1);
        float corr0 = __expf(mx0 - nm0), corr1 = __expf(mx1 - nm1);
        mx0 = nm0; mx1 = nm1;

        float sum0 = 0.f, sum1 = 0.f;
        #pragma unroll
        for (int nt = 0; nt < 8; nt++) {
            accs[nt][0] = __expf(accs[nt][0] - nm0);
            accs[nt][1] = __expf(accs[nt][1] - nm0);
            accs[nt][2] = __expf(accs[nt][2] - nm1);
            accs[nt][3] = __expf(accs[nt][3] - nm1);
            sum0 += accs[nt][0] + accs[nt][1];
            sum1 += accs[nt][2] + accs[nt][3];
        }
        sum0 += __shfl_xor_sync(0xffffffffu, sum0, 1);
        sum0 += __shfl_xor_sync(0xffffffffu, sum0, 2);
        sum1 += __shfl_xor_sync(0xffffffffu, sum1, 1);
        sum1 += __shfl_xor_sync(0xffffffffu, sum1, 2);
        l0 = l0 * corr0 + sum0;
        l1 = l1 * corr1 + sum1;
        #pragma unroll
        for (int nt = 0; nt < 8; nt++) {
            acco[nt][0] *= corr0; acco[nt][1] *= corr0;
            acco[nt][2] *= corr1; acco[nt][3] *= corr1;
        }

        uint32_t pf[4][4];
        #pragma unroll
        for (int ks = 0; ks < 4; ks++) {
            __half2 h0 = __floats2half2_rn(accs[2*ks][0],   accs[2*ks][1]);
            __half2 h1 = __floats2half2_rn(accs[2*ks][2],   accs[2*ks][3]);
            __half2 h2 = __floats2half2_rn(accs[2*ks+1][0], accs[2*ks+1][1]);
            __half2 h3 = __floats2half2_rn(accs[2*ks+1][2], accs[2*ks+1][3]);
            pf[ks][0] = *reinterpret_cast<uint32_t*>(&h0);
            pf[ks][1] = *reinterpret_cast<uint32_t*>(&h1);
            pf[ks][2] = *reinterpret_cast<uint32_t*>(&h2);
            pf[ks][3] = *reinterpret_cast<uint32_t*>(&h3);
        }

        // O += P @ V
        #pragma unroll
        for (int np = 0; np < 4; np++) {
            #pragma unroll
            for (int ks = 0; ks < 4; ks++) {
                uint32_t bfr[4];
                ldsm_x4(bfr, sV + (uint32_t)(np * 16 * AST + ks * 16) * 2u);
                mma_f16(acco[2*np],   pf[ks], &bfr[0]);
                mma_f16(acco[2*np+1], pf[ks], &bfr[2]);
            }
        }
        __syncthreads();
    }

    float inv0 = 1.0f / l0, inv1 = 1.0f / l1;
    __half* y0 = y + (size_t)(tok0 + r0) * (NH * HD) + h * HD;
    __half* y1 = y + (size_t)(tok0 + r1) * (NH * HD) + h * HD;
    #pragma unroll
    for (int nt = 0; nt < 8; nt++) {
        int col = nt * 8 + lc * 2;
        *reinterpret_cast<__half2*>(y0 + col) = __floats2half2_rn(acco[nt][0]*inv0, acco[nt][1]*inv0);
        *reinterpret_cast<__half2*>(y1 + col) = __floats2half2_rn(acco[nt][2]*inv1, acco[nt][3]*inv1);
    }
}

// ---------------- launch ----------------
extern "C" void kernel_launch(void* const* d_in, const int* in_sizes, int n_in,
                              void* d_out, int out_size) {
    const float* x          = (const float*)d_in[0];
    const float* wq         = (const float*)d_in[1];
    const float* wk         = (const float*)d_in[2];
    const float* wv         = (const float*)d_in[3];
    const float* wo         = (const float*)d_in[4];
    const float* w1         = (const float*)d_in[5];
    const float* w2         = (const float*)d_in[6];
    const float* w3         = (const float*)d_in[7];
    const float* q_norm_w   = (const float*)d_in[8];
    const float* k_norm_w   = (const float*)d_in[9];
    const float* attn_norm_w= (const float*)d_in[10];
    const float* ffn_norm_w = (const float*)d_in[11];
    const float* attn_scale = (const float*)d_in[12];
    const float* ffn_scale  = (const float*)d_in[13];
    float* out = (float*)d_out;

    float* h;
    __half *xnh, *qh, *kh, *vth, *yh, *uh, *ph;
    __half *hwq, *hwk, *hwv, *hwo, *hw1, *hw2, *hw3;
    cudaGetSymbolAddress((void**)&h,   g_h);
    cudaGetSymbolAddress((void**)&xnh, g_xnh);
    cudaGetSymbolAddress((void**)&qh,  g_qh);
    cudaGetSymbolAddress((void**)&kh,  g_kh);
    cudaGetSymbolAddress((void**)&vth, g_vt);
    cudaGetSymbolAddress((void**)&yh,  g_yh);
    cudaGetSymbolAddress((void**)&uh,  g_uh);
    cudaGetSymbolAddress((void**)&ph,  g_ph);
    cudaGetSymbolAddress((void**)&hwq, g_wq);
    cudaGetSymbolAddress((void**)&hwk, g_wk);
    cudaGetSymbolAddress((void**)&hwv, g_wv);
    cudaGetSymbolAddress((void**)&hwo, g_wo);
    cudaGetSymbolAddress((void**)&hw1, g_w1);
    cudaGetSymbolAddress((void**)&hw2, g_w2);
    cudaGetSymbolAddress((void**)&hw3, g_w3);

    static bool attr_done = false;
    if (!attr_done) {
        cudaFuncSetAttribute((const void*)gemm_mma<0, float>,  cudaFuncAttributeMaxDynamicSharedMemorySize, GSMEM_BYTES);
        cudaFuncSetAttribute((const void*)gemm_mma<0, __half>, cudaFuncAttributeMaxDynamicSharedMemorySize, GSMEM_BYTES);
        cudaFuncSetAttribute((const void*)gemm_mma<1, float>,  cudaFuncAttributeMaxDynamicSharedMemorySize, GSMEM_BYTES);
        cudaFuncSetAttribute((const void*)gemm_mma<2, __half>, cudaFuncAttributeMaxDynamicSharedMemorySize, GSMEM_BYTES);
        cudaFuncSetAttribute((const void*)gemm_mma<3, __half>, cudaFuncAttributeMaxDynamicSharedMemorySize, GSMEM_BYTES);
        cudaFuncSetAttribute((const void*)attn_mma, cudaFuncAttributeMaxDynamicSharedMemorySize, ASMEM_BYTES);
        attr_done = true;
    }

    // 0. convert weights fp32 -> fp16 (single fused kernel)
    {
        F2HDescs dd;
        const float* srcs[7] = {wq, wk, wv, wo, w1, w2, w3};
        __half* dsts[7] = {hwq, hwk, hwv, hwo, hw1, hw2, hw3};
        int ns[7] = {NH*HD*DIM/4, KVH*HD*DIM/4, KVH*HD*DIM/4, DIM*NH*HD/4,
                     HID*DIM/4, DIM*HID/4, HID*DIM/4};
        int total = 0;
        for (int j = 0; j < 7; j++) {
            dd.s[j] = (const float4*)srcs[j];
            dd.d[j] = (__half2*)dsts[j];
            dd.n4[j] = ns[j];
            total += ns[j];
        }
        f2h_all<<<(total + 255) / 256, 256>>>(dd);
    }

    const int MB = MROWS / GBM;   // 32

    // 1. xn = rmsnorm(x, attn_norm_w) -> fp16
    rmsnorm_kernel<<<MROWS, 256>>>(x, attn_norm_w, xnh, 1e-5f);

    // 2. q projection (fp16); k normal + v transposed dual launch
    gemm_mma<0, __half><<<dim3(DIM/GBN, MB), 256, GSMEM_BYTES>>>(
        xnh, hwq, qh, DIM, DIM, nullptr, nullptr, nullptr, nullptr, nullptr);
    gemm_mma<3, __half><<<dim3(4, MB), 256, GSMEM_BYTES>>>(
        xnh, hwk, kh, DIM, KVH*HD, nullptr, nullptr, nullptr, hwv, vth);

    // 3. head rmsnorm: q (x0.125 folded), k
    headnorm_h<<<(MROWS * NH) / 8, 256>>>(qh, q_norm_w, 0.125f);
    headnorm_h<<<(MROWS * KVH) / 8, 256>>>(kh, k_norm_w, 1.0f);

    // 4. flash attention (fp16 mma + ldmatrix)
    attn_mma<<<dim3(TT/64, NH, BB), 128, ASMEM_BYTES>>>(qh, kh, vth, yh);

    // 5. h = x + (y @ wo.T) * attn_scale   (fp32 out)
    gemm_mma<1, float><<<dim3(DIM/GBN, MB), 256, GSMEM_BYTES>>>(
        yh, hwo, h, DIM, DIM, x, attn_scale, nullptr, nullptr, nullptr);

    // 6. hn = rmsnorm(h, ffn_norm_w) -> fp16
    rmsnorm_kernel<<<MROWS, 256>>>(h, ffn_norm_w, xnh, 1e-5f);

    // 7. u = hn @ w1.T (fp16); p = silu(u) * (hn @ w3.T) (fp16)
    gemm_mma<0, __half><<<dim3(HID/GBN, MB), 256, GSMEM_BYTES>>>(
        xnh, hw1, uh, DIM, HID, nullptr, nullptr, nullptr, nullptr, nullptr);
    gemm_mma<2, __half><<<dim3(HID/GBN, MB), 256, GSMEM_BYTES>>>(
        xnh, hw3, ph, DIM, HID, nullptr, nullptr, uh, nullptr, nullptr);

    // 8. out = h + (p @ w2.T) * ffn_scale  (fp32 out)
    gemm_mma<1, float><<<dim3(DIM/GBN, MB), 256, GSMEM_BYTES>>>(
        ph, hw2, out, HID, DIM, h, ffn_scale, nullptr, nullptr, nullptr);
}

// round 9
// speedup vs baseline: 6.9085x; 1.0032x over previous
#include <cuda_runtime.h>
#include <cuda_fp16.h>
#include <math.h>
#include <stdint.h>

// Problem constants
#define BB   2
#define TT   2048
#define MROWS (BB*TT)        // 4096
#define DIM  1024
#define HID  4096
#define NH   16
#define KVH  4
#define HD   64
#define WIN  512

// ---------------- scratch (device globals; no allocs allowed) ----------------
__device__ float  g_h [MROWS * DIM];      // residual 1 (fp32)
__device__ __half g_xnh[MROWS * DIM];     // rmsnorm out (xn / hn)
__device__ __half g_qh [MROWS * NH * HD];
__device__ __half g_kh [MROWS * KVH * HD];
__device__ __half g_vt [KVH * HD * MROWS];  // V transposed: [channel][token]
__device__ __half g_yh [MROWS * NH * HD]; // attention out
__device__ __half g_uh [MROWS * HID];     // w1 out (pre-activation)
__device__ __half g_ph [MROWS * HID];     // silu(u)*g
// fp16 weights
__device__ __half g_wq[NH*HD * DIM];
__device__ __half g_wk[KVH*HD * DIM];
__device__ __half g_wv[KVH*HD * DIM];
__device__ __half g_wo[DIM * NH*HD];
__device__ __half g_w1[HID * DIM];
__device__ __half g_w2[DIM * HID];
__device__ __half g_w3[HID * DIM];

// ================= helpers =================
__device__ __forceinline__ uint32_t smem_u32(const void* p) {
    uint32_t a;
    asm("{ .reg .u64 t; cvta.to.shared.u64 t, %1; cvt.u32.u64 %0, t; }" : "=r"(a) : "l"(p));
    return a;
}
__device__ __forceinline__ void cp_async16(uint32_t dst, const void* src) {
    asm volatile("cp.async.cg.shared.global [%0], [%1], 16;" :: "r"(dst), "l"(src) : "memory");
}
__device__ __forceinline__ void cp_commit() {
    asm volatile("cp.async.commit_group;" ::: "memory");
}
__device__ __forceinline__ void cp_wait2() {
    asm volatile("cp.async.wait_group 2;" ::: "memory");
}
__device__ __forceinline__ void cp_wait1() {
    asm volatile("cp.async.wait_group 1;" ::: "memory");
}
__device__ __forceinline__ void cp_wait0() {
    asm volatile("cp.async.wait_group 0;" ::: "memory");
}
__device__ __forceinline__ void mma_f16(float* d, const uint32_t* a, const uint32_t* b) {
    asm volatile(
        "mma.sync.aligned.m16n8k16.row.col.f32.f16.f16.f32 "
        "{%0,%1,%2,%3}, {%4,%5,%6,%7}, {%8,%9}, {%0,%1,%2,%3};"
        : "+f"(d[0]), "+f"(d[1]), "+f"(d[2]), "+f"(d[3])
        : "r"(a[0]), "r"(a[1]), "r"(a[2]), "r"(a[3]), "r"(b[0]), "r"(b[1]));
}
__device__ __forceinline__ void ldsm_x4(uint32_t* r, uint32_t addr) {
    asm volatile("ldmatrix.sync.aligned.m8n8.x4.shared.b16 {%0,%1,%2,%3}, [%4];"
                 : "=r"(r[0]), "=r"(r[1]), "=r"(r[2]), "=r"(r[3]) : "r"(addr));
}

// ---------------- fused fp32 -> fp16 convert (all 7 weights) ----------------
struct F2HDescs {
    const float4* s[7];
    __half2* d[7];
    int n4[7];
};
__global__ void f2h_all(F2HDescs dd) {
    int i = blockIdx.x * 256 + threadIdx.x;
    #pragma unroll
    for (int j = 0; j < 7; j++) {
        if (i < dd.n4[j]) {
            float4 v = dd.s[j][i];
            dd.d[j][2*i]   = __floats2half2_rn(v.x, v.y);
            dd.d[j][2*i+1] = __floats2half2_rn(v.z, v.w);
            return;
        }
        i -= dd.n4[j];
    }
}

// ================= fp16 mma.sync GEMM (ldmatrix, 4-stage, 1 barrier/iter) ====
// C[M,N] = A[M,K] @ W[N,K]^T. BM=128,BN=128,BK=32. 2 CTAs/SM.
// EPI: 0 plain; 1 res+acc*scale (float); 2 silu(upre)*acc (half);
//      3 dual KV: blocks 0,1 -> K half; blocks 2,3 -> V transposed into C2
#define GBM 128
#define GBN 128
#define GBK 32
#define HSTRIDE 40
#define TILE_HALFS (GBM*HSTRIDE)        // 5120
#define STAGE_HALFS (2*TILE_HALFS)      // 10240
#define STAGE_BYTES (STAGE_HALFS*2)     // 20480
#define GSTAGES 4
#define GSMEM_BYTES (GSTAGES*STAGE_BYTES)  // 81920

template<int EPI, typename TO>
__global__ void __launch_bounds__(256, 2)
gemm_mma(const __half* __restrict__ A, const __half* __restrict__ W,
         TO* __restrict__ C, int K, int N,
         const float* __restrict__ res, const float* __restrict__ scale,
         const __half* __restrict__ upre,
         const __half* __restrict__ W2, __half* __restrict__ C2) {
    extern __shared__ __half sm[];
    const uint32_t sb = smem_u32(sm);
    const int tid = threadIdx.x;
    const int wid = tid >> 5, lane = tid & 31;
    const int wm = wid & 1, wn = wid >> 1;
    const int lr = lane >> 2, lc = lane & 3;

    const __half* Wp = W;
    TO* Cp = C;
    bool second = false;
    int bcol0;
    if (W2 != nullptr) {
        if (blockIdx.x >> 1) { Wp = W2; second = true; }
        bcol0 = (blockIdx.x & 1) * GBN;
    } else {
        bcol0 = blockIdx.x * GBN;
    }
    const int brow0 = blockIdx.y * GBM;

    uint32_t aoff[2], boff[2];
    const __half* ag[2];
    const __half* bg[2];
    #pragma unroll
    for (int j = 0; j < 2; j++) {
        int f = tid + j * 256;
        int row = f >> 2, kc = (f & 3) * 8;
        aoff[j] = (uint32_t)(row * HSTRIDE + kc) * 2u;
        boff[j] = aoff[j] + TILE_HALFS * 2u;
        ag[j] = A  + (size_t)(brow0 + row) * K + kc;
        bg[j] = Wp + (size_t)(bcol0 + row) * K + kc;
    }

    // ldmatrix per-thread base offsets (within a stage), in bytes
    const uint32_t a_lm = (uint32_t)((wm * 64 + (lane & 15)) * HSTRIDE + ((lane >> 4) << 3)) * 2u;
    const uint32_t b_lm = (uint32_t)(TILE_HALFS +
                         (wn * 32 + (lane & 7) + ((lane >> 4) << 3)) * HSTRIDE +
                         (((lane >> 3) & 1) << 3)) * 2u;

    const int NC = K / GBK;

    // prologue: fill GSTAGES-1 stages
    #pragma unroll
    for (int s = 0; s < GSTAGES - 1; s++) {
        uint32_t so = sb + s * STAGE_BYTES;
        int k0 = s * GBK;
        #pragma unroll
        for (int j = 0; j < 2; j++) cp_async16(so + aoff[j], ag[j] + k0);
        #pragma unroll
        for (int j = 0; j < 2; j++) cp_async16(so + boff[j], bg[j] + k0);
        cp_commit();
    }

    float acc[4][4][4];
    #pragma unroll
    for (int mt = 0; mt < 4; mt++)
        #pragma unroll
        for (int nt = 0; nt < 4; nt++)
            #pragma unroll
            for (int r = 0; r < 4; r++) acc[mt][nt][r] = 0.f;

    #pragma unroll 1
    for (int i = 0; i < NC; i++) {
        cp_wait2();            // chunks <= i complete (S-2 = 2 pending allowed)
        __syncthreads();       // visibility + stage (i-1)%S fully consumed
        // prefetch chunk i+S-1 into stage (i+S-1)%S == (i-1)%S
        if (i + GSTAGES - 1 < NC) {
            uint32_t so = sb + ((i + GSTAGES - 1) % GSTAGES) * STAGE_BYTES;
            int k0 = (i + GSTAGES - 1) * GBK;
            #pragma unroll
            for (int j = 0; j < 2; j++) cp_async16(so + aoff[j], ag[j] + k0);
            #pragma unroll
            for (int j = 0; j < 2; j++) cp_async16(so + boff[j], bg[j] + k0);
        }
        cp_commit();           // unconditional: keeps wait arithmetic exact

        const int p = i % GSTAGES;
        const uint32_t sA = sb + p * STAGE_BYTES + a_lm;
        const uint32_t sB = sb + p * STAGE_BYTES + b_lm;
        #pragma unroll
        for (int ks = 0; ks < 2; ks++) {
            uint32_t a[4][4], b[2][4];
            #pragma unroll
            for (int mt = 0; mt < 4; mt++)
                ldsm_x4(a[mt], sA + (uint32_t)(mt * 16 * HSTRIDE + ks * 16) * 2u);
            #pragma unroll
            for (int np = 0; np < 2; np++)
                ldsm_x4(b[np], sB + (uint32_t)(np * 16 * HSTRIDE + ks * 16) * 2u);
            #pragma unroll
            for (int mt = 0; mt < 4; mt++)
                #pragma unroll
                for (int nt = 0; nt < 4; nt++)
                    mma_f16(acc[mt][nt], a[mt], &b[nt >> 1][(nt & 1) * 2]);
        }
    }

    #pragma unroll
    for (int mt = 0; mt < 4; mt++) {
        #pragma unroll
        for (int half = 0; half < 2; half++) {
            int row = brow0 + wm * 64 + mt * 16 + half * 8 + lr;
            TO* crow = Cp + (size_t)row * N;
            #pragma unroll
            for (int nt = 0; nt < 4; nt++) {
                int col = bcol0 + wn * 32 + nt * 8 + lc * 2;
                float d0 = acc[mt][nt][half * 2 + 0];
                float d1 = acc[mt][nt][half * 2 + 1];
                if (EPI == 0) {
                    if (sizeof(TO) == 2) {
                        *reinterpret_cast<__half2*>((__half*)crow + col) = __floats2half2_rn(d0, d1);
                    } else {
                        *reinterpret_cast<float2*>((float*)crow + col) = make_float2(d0, d1);
                    }
                } else if (EPI == 1) {
                    float o0 = res[(size_t)row * N + col]     + d0 * scale[col];
                    float o1 = res[(size_t)row * N + col + 1] + d1 * scale[col + 1];
                    *reinterpret_cast<float2*>((float*)crow + col) = make_float2(o0, o1);
                } else if (EPI == 2) {
                    float u0 = __half2float(upre[(size_t)row * N + col]);
                    float u1 = __half2float(upre[(size_t)row * N + col + 1]);
                    float s0 = u0 / (1.0f + __expf(-u0));
                    float s1 = u1 / (1.0f + __expf(-u1));
                    *reinterpret_cast<__half2*>((__half*)crow + col) = __floats2half2_rn(s0 * d0, s1 * d1);
                } else {  // EPI == 3
                    if (!second) {
                        *reinterpret_cast<__half2*>((__half*)crow + col) = __floats2half2_rn(d0, d1);
                    } else {
                        C2[(size_t)col * MROWS + row]       = __float2half_rn(d0);
                        C2[(size_t)(col + 1) * MROWS + row] = __float2half_rn(d1);
                    }
                }
            }
        }
    }
}

// ---------------- row RMSNorm over DIM=1024 (fp32 in, fp16 out) ----------------
__global__ void rmsnorm_kernel(const float* __restrict__ x,
                               const float* __restrict__ w,
                               __half* __restrict__ out, float eps) {
    int row = blockIdx.x;
    int tid = threadIdx.x;
    const float4* xr = reinterpret_cast<const float4*>(x + (size_t)row * DIM);
    float4 v = xr[tid];
    float ss = v.x*v.x + v.y*v.y + v.z*v.z + v.w*v.w;
    #pragma unroll
    for (int o = 16; o; o >>= 1) ss += __shfl_xor_sync(0xffffffffu, ss, o);
    __shared__ float red[8];
    __shared__ float stot;
    int lane = tid & 31, wid = tid >> 5;
    if (lane == 0) red[wid] = ss;
    __syncthreads();
    if (tid == 0) {
        float s = 0.f;
        #pragma unroll
        for (int i = 0; i < 8; i++) s += red[i];
        stot = rsqrtf(s * (1.0f / DIM) + eps);
    }
    __syncthreads();
    float sc = stot;
    const float4* wr = reinterpret_cast<const float4*>(w);
    float4 wv = wr[tid];
    __half2 h0 = __floats2half2_rn(v.x*sc*wv.x, v.y*sc*wv.y);
    __half2 h1 = __floats2half2_rn(v.z*sc*wv.z, v.w*sc*wv.w);
    __half2* op = reinterpret_cast<__half2*>(out + (size_t)row * DIM) + tid * 2;
    op[0] = h0; op[1] = h1;
}

// ---------------- per-head RMSNorm over HD=64 (fp16 in-place) ----------------
__global__ void headnorm_h(__half* __restrict__ buf, const float* __restrict__ w,
                           float post) {
    int warp = threadIdx.x >> 5;
    int lane = threadIdx.x & 31;
    size_t r = (size_t)blockIdx.x * 8 + warp;
    __half2* p = reinterpret_cast<__half2*>(buf + r * HD) + lane;
    float2 v = __half22float2(*p);
    float ss = v.x*v.x + v.y*v.y;
    #pragma unroll
    for (int o = 16; o; o >>= 1) ss += __shfl_xor_sync(0xffffffffu, ss, o);
    float sc = rsqrtf(ss * (1.0f / HD) + 1e-6f) * post;
    *p = __floats2half2_rn(v.x * sc * w[2*lane], v.y * sc * w[2*lane+1]);
}

// ---------------- fp16 mma flash attention (ldmatrix) ----------------
// grid (TT/64, NH, BB), 128 threads (4 warps, 16 q-rows each).
#define AST 72
#define A_K0 (64*AST)
#define A_STG (2*64*AST)
#define ASMEM_HALFS (64*AST + 2*2*64*AST)
#define ASMEM_BYTES (ASMEM_HALFS*2)        // 46080

__global__ void __launch_bounds__(128, 3)
attn_mma(const __half* __restrict__ q, const __half* __restrict__ k,
         const __half* __restrict__ vt, __half* __restrict__ y) {
    extern __shared__ __half asmem[];
    const uint32_t sb = smem_u32(asmem);
    const int m   = blockIdx.x;
    const int h   = blockIdx.y;
    const int b   = blockIdx.z;
    const int kvh = h >> 2;
    const int tid = threadIdx.x;
    const int w   = tid >> 5, lane = tid & 31;
    const int lr  = lane >> 2, lc = lane & 3;
    const int tok0 = b * TT;

    const int tlo = (m >= 8) ? m - 8 : 0;

    const uint32_t q_lm = (uint32_t)((w * 16 + (lane & 15)) * AST + ((lane >> 4) << 3)) * 2u;
    const uint32_t kv_lm = (uint32_t)(((lane & 7) + ((lane >> 4) << 3)) * AST +
                                      (((lane >> 3) & 1) << 3)) * 2u;

    {
        #pragma unroll
        for (int i = 0; i < 4; i++) {
            int c = tid + i * 128;
            int row = c >> 3, cc = c & 7;
            cp_async16(sb + (uint32_t)(row * AST + cc * 8) * 2,
                       q + (size_t)(tok0 + m * 64 + row) * (NH * HD) + h * HD + cc * 8);
        }
        #pragma unroll
        for (int i = 0; i < 4; i++) {
            int c = tid + i * 128;
            int row = c >> 3, cc = c & 7;
            cp_async16(sb + (uint32_t)(A_K0 + row * AST + cc * 8) * 2,
                       k + (size_t)(tok0 + tlo * 64 + row) * (KVH * HD) + kvh * HD + cc * 8);
            cp_async16(sb + (uint32_t)(A_K0 + 64 * AST + row * AST + cc * 8) * 2,
                       vt + (size_t)(kvh * HD + row) * MROWS + tok0 + tlo * 64 + cc * 8);
        }
        cp_commit();
    }

    uint32_t qf[4][4];
    float acco[8][4];
    #pragma unroll
    for (int nt = 0; nt < 8; nt++)
        #pragma unroll
        for (int r = 0; r < 4; r++) acco[nt][r] = 0.f;
    float mx0 = -INFINITY, mx1 = -INFINITY, l0 = 0.f, l1 = 0.f;

    const int r0 = m * 64 + w * 16 + lr;
    const int r1 = r0 + 8;

    for (int t = tlo; t <= m; t++) {
        const int s = (t - tlo) & 1;
        if (t < m) {
            const int sn = s ^ 1;
            #pragma unroll
            for (int i = 0; i < 4; i++) {
                int c = tid + i * 128;
                int row = c >> 3, cc = c & 7;
                cp_async16(sb + (uint32_t)(A_K0 + sn * A_STG + row * AST + cc * 8) * 2,
                           k + (size_t)(tok0 + (t+1) * 64 + row) * (KVH * HD) + kvh * HD + cc * 8);
                cp_async16(sb + (uint32_t)(A_K0 + sn * A_STG + 64 * AST + row * AST + cc * 8) * 2,
                           vt + (size_t)(kvh * HD + row) * MROWS + tok0 + (t+1) * 64 + cc * 8);
            }
        }
        cp_commit();
        if (t < m) cp_wait1(); else cp_wait0();
        __syncthreads();

        if (t == tlo) {
            #pragma unroll
            for (int ks = 0; ks < 4; ks++)
                ldsm_x4(qf[ks], sb + q_lm + (uint32_t)(ks * 16) * 2u);
        }

        const uint32_t sK = sb + (uint32_t)(A_K0 + s * A_STG) * 2u + kv_lm;
        const uint32_t sV = sK + (uint32_t)(64 * AST) * 2u;

        float accs[8][4];
        #pragma unroll
        for (int nt = 0; nt < 8; nt++)
            #pragma unroll
            for (int r = 0; r < 4; r++) accs[nt][r] = 0.f;
        #pragma unroll
        for (int np = 0; np < 4; np++) {
            #pragma unroll
            for (int ks = 0; ks < 4; ks++) {
                uint32_t bfr[4];
                ldsm_x4(bfr, sK + (uint32_t)(np * 16 * AST + ks * 16) * 2u);
                mma_f16(accs[2*np],   qf[ks], &bfr[0]);
                mma_f16(accs[2*np+1], qf[ks], &bfr[2]);
            }
        }

        if (t == m || t + 8 == m) {
            #pragma unroll
            for (int nt = 0; nt < 8; nt++) {
                int c0 = t * 64 + nt * 8 + lc * 2;
                #pragma unroll
                for (int r = 0; r < 4; r++) {
                    int row = (r < 2) ? r0 : r1;
                    int col = c0 + (r & 1);
                    bool valid = (col <= row) && (col + WIN > row);
                    if (!valid) accs[nt][r] = -1e30f;
                }
            }
        }

        float tm0 = -1e30f, tm1 = -1e30f;
        #pragma unroll
        for (int nt = 0; nt < 8; nt++) {
            tm0 = fmaxf(tm0, fmaxf(accs[nt][0], accs[nt][1]));
            tm1 = fmaxf(tm1, fmaxf(accs[nt][2], accs[nt][3]));
        }
        tm0 = fmaxf(tm0, __shfl_xor_sync(0xffffffffu, tm0, 1));
        tm0 = fmaxf(tm0, __shfl_xor_sync(0xffffffffu, tm0, 2));
        tm1 = fmaxf(tm1, __shfl_xor_sync(0xffffffffu, tm1, 1));
        tm1 = fmaxf(tm1, __shfl_xor_sync(0xffffffffu, tm1, 2));
        float nm0 = fmaxf(mx0, tm0), nm1 = fmaxf(mx1, tm1);
        float corr0 = __expf(mx0 - nm0), corr1 = __expf(mx1 - nm1);
        mx0 = nm0; mx1 = nm1;

        float sum0 = 0.f, sum1 = 0.f;
        #pragma unroll
        for (int nt = 0; nt < 8; nt++) {
            accs[nt][0] = __expf(accs[nt][0] - nm0);
            accs[nt][1] = __expf(accs[nt][1] - nm0);
            accs[nt][2] = __expf(accs[nt][2] - nm1);
            accs[nt][3] = __expf(accs[nt][3] - nm1);
            sum0 += accs[nt][0] + accs[nt][1];
            sum1 += accs[nt][2] + accs[nt][3];
        }
        sum0 += __shfl_xor_sync(0xffffffffu, sum0, 1);
        sum0 += __shfl_xor_sync(0xffffffffu, sum0, 2);
        sum1 += __shfl_xor_sync(0xffffffffu, sum1, 1);
        sum1 += __shfl_xor_sync(0xffffffffu, sum1, 2);
        l0 = l0 * corr0 + sum0;
        l1 = l1 * corr1 + sum1;
        #pragma unroll
        for (int nt = 0; nt < 8; nt++) {
            acco[nt][0] *= corr0; acco[nt][1] *= corr0;
            acco[nt][2] *= corr1; acco[nt][3] *= corr1;
        }

        uint32_t pf[4][4];
        #pragma unroll
        for (int ks = 0; ks < 4; ks++) {
            __half2 h0 = __floats2half2_rn(accs[2*ks][0],   accs[2*ks][1]);
            __half2 h1 = __floats2half2_rn(accs[2*ks][2],   accs[2*ks][3]);
            __half2 h2 = __floats2half2_rn(accs[2*ks+1][0], accs[2*ks+1][1]);
            __half2 h3 = __floats2half2_rn(accs[2*ks+1][2], accs[2*ks+1][3]);
            pf[ks][0] = *reinterpret_cast<uint32_t*>(&h0);
            pf[ks][1] = *reinterpret_cast<uint32_t*>(&h1);
            pf[ks][2] = *reinterpret_cast<uint32_t*>(&h2);
            pf[ks][3] = *reinterpret_cast<uint32_t*>(&h3);
        }

        #pragma unroll
        for (int np = 0; np < 4; np++) {
            #pragma unroll
            for (int ks = 0; ks < 4; ks++) {
                uint32_t bfr[4];
                ldsm_x4(bfr, sV + (uint32_t)(np * 16 * AST + ks * 16) * 2u);
                mma_f16(acco[2*np],   pf[ks], &bfr[0]);
                mma_f16(acco[2*np+1], pf[ks], &bfr[2]);
            }
        }
        __syncthreads();
    }

    float inv0 = 1.0f / l0, inv1 = 1.0f / l1;
    __half* y0 = y + (size_t)(tok0 + r0) * (NH * HD) + h * HD;
    __half* y1 = y + (size_t)(tok0 + r1) * (NH * HD) + h * HD;
    #pragma unroll
    for (int nt = 0; nt < 8; nt++) {
        int col = nt * 8 + lc * 2;
        *reinterpret_cast<__half2*>(y0 + col) = __floats2half2_rn(acco[nt][0]*inv0, acco[nt][1]*inv0);
        *reinterpret_cast<__half2*>(y1 + col) = __floats2half2_rn(acco[nt][2]*inv1, acco[nt][3]*inv1);
    }
}

// ---------------- launch ----------------
extern "C" void kernel_launch(void* const* d_in, const int* in_sizes, int n_in,
                              void* d_out, int out_size) {
    const float* x          = (const float*)d_in[0];
    const float* wq         = (const float*)d_in[1];
    const float* wk         = (const float*)d_in[2];
    const float* wv         = (const float*)d_in[3];
    const float* wo         = (const float*)d_in[4];
    const float* w1         = (const float*)d_in[5];
    const float* w2         = (const float*)d_in[6];
    const float* w3         = (const float*)d_in[7];
    const float* q_norm_w   = (const float*)d_in[8];
    const float* k_norm_w   = (const float*)d_in[9];
    const float* attn_norm_w= (const float*)d_in[10];
    const float* ffn_norm_w = (const float*)d_in[11];
    const float* attn_scale = (const float*)d_in[12];
    const float* ffn_scale  = (const float*)d_in[13];
    float* out = (float*)d_out;

    float* h;
    __half *xnh, *qh, *kh, *vth, *yh, *uh, *ph;
    __half *hwq, *hwk, *hwv, *hwo, *hw1, *hw2, *hw3;
    cudaGetSymbolAddress((void**)&h,   g_h);
    cudaGetSymbolAddress((void**)&xnh, g_xnh);
    cudaGetSymbolAddress((void**)&qh,  g_qh);
    cudaGetSymbolAddress((void**)&kh,  g_kh);
    cudaGetSymbolAddress((void**)&vth, g_vt);
    cudaGetSymbolAddress((void**)&yh,  g_yh);
    cudaGetSymbolAddress((void**)&uh,  g_uh);
    cudaGetSymbolAddress((void**)&ph,  g_ph);
    cudaGetSymbolAddress((void**)&hwq, g_wq);
    cudaGetSymbolAddress((void**)&hwk, g_wk);
    cudaGetSymbolAddress((void**)&hwv, g_wv);
    cudaGetSymbolAddress((void**)&hwo, g_wo);
    cudaGetSymbolAddress((void**)&hw1, g_w1);
    cudaGetSymbolAddress((void**)&hw2, g_w2);
    cudaGetSymbolAddress((void**)&hw3, g_w3);

    static bool attr_done = false;
    if (!attr_done) {
        cudaFuncSetAttribute((const void*)gemm_mma<0, float>,  cudaFuncAttributeMaxDynamicSharedMemorySize, GSMEM_BYTES);
        cudaFuncSetAttribute((const void*)gemm_mma<0, __half>, cudaFuncAttributeMaxDynamicSharedMemorySize, GSMEM_BYTES);
        cudaFuncSetAttribute((const void*)gemm_mma<1, float>,  cudaFuncAttributeMaxDynamicSharedMemorySize, GSMEM_BYTES);
        cudaFuncSetAttribute((const void*)gemm_mma<2, __half>, cudaFuncAttributeMaxDynamicSharedMemorySize, GSMEM_BYTES);
        cudaFuncSetAttribute((const void*)gemm_mma<3, __half>, cudaFuncAttributeMaxDynamicSharedMemorySize, GSMEM_BYTES);
        cudaFuncSetAttribute((const void*)attn_mma, cudaFuncAttributeMaxDynamicSharedMemorySize, ASMEM_BYTES);
        attr_done = true;
    }

    // 0. convert weights fp32 -> fp16 (single fused kernel)
    {
        F2HDescs dd;
        const float* srcs[7] = {wq, wk, wv, wo, w1, w2, w3};
        __half* dsts[7] = {hwq, hwk, hwv, hwo, hw1, hw2, hw3};
        int ns[7] = {NH*HD*DIM/4, KVH*HD*DIM/4, KVH*HD*DIM/4, DIM*NH*HD/4,
                     HID*DIM/4, DIM*HID/4, HID*DIM/4};
        int total = 0;
        for (int j = 0; j < 7; j++) {
            dd.s[j] = (const float4*)srcs[j];
            dd.d[j] = (__half2*)dsts[j];
            dd.n4[j] = ns[j];
            total += ns[j];
        }
        f2h_all<<<(total + 255) / 256, 256>>>(dd);
    }

    const int MB = MROWS / GBM;   // 32

    // 1. xn = rmsnorm(x, attn_norm_w) -> fp16
    rmsnorm_kernel<<<MROWS, 256>>>(x, attn_norm_w, xnh, 1e-5f);

    // 2. q projection (fp16); k normal + v transposed dual launch
    gemm_mma<0, __half><<<dim3(DIM/GBN, MB), 256, GSMEM_BYTES>>>(
        xnh, hwq, qh, DIM, DIM, nullptr, nullptr, nullptr, nullptr, nullptr);
    gemm_mma<3, __half><<<dim3(4, MB), 256, GSMEM_BYTES>>>(
        xnh, hwk, kh, DIM, KVH*HD, nullptr, nullptr, nullptr, hwv, vth);

    // 3. head rmsnorm: q (x0.125 folded), k
    headnorm_h<<<(MROWS * NH) / 8, 256>>>(qh, q_norm_w, 0.125f);
    headnorm_h<<<(MROWS * KVH) / 8, 256>>>(kh, k_norm_w, 1.0f);

    // 4. flash attention (fp16 mma + ldmatrix)
    attn_mma<<<dim3(TT/64, NH, BB), 128, ASMEM_BYTES>>>(qh, kh, vth, yh);

    // 5. h = x + (y @ wo.T) * attn_scale   (fp32 out)
    gemm_mma<1, float><<<dim3(DIM/GBN, MB), 256, GSMEM_BYTES>>>(
        yh, hwo, h, DIM, DIM, x, attn_scale, nullptr, nullptr, nullptr);

    // 6. hn = rmsnorm(h, ffn_norm_w) -> fp16
    rmsnorm_kernel<<<MROWS, 256>>>(h, ffn_norm_w, xnh, 1e-5f);

    // 7. u = hn @ w1.T (fp16); p = silu(u) * (hn @ w3.T) (fp16)
    gemm_mma<0, __half><<<dim3(HID/GBN, MB), 256, GSMEM_BYTES>>>(
        xnh, hw1, uh, DIM, HID, nullptr, nullptr, nullptr, nullptr, nullptr);
    gemm_mma<2, __half><<<dim3(HID/GBN, MB), 256, GSMEM_BYTES>>>(
        xnh, hw3, ph, DIM, HID, nullptr, nullptr, uh, nullptr, nullptr);

    // 8. out = h + (p @ w2.T) * ffn_scale  (fp32 out)
    gemm_mma<1, float><<<dim3(DIM/GBN, MB), 256, GSMEM_BYTES>>>(
        ph, hw2, out, HID, DIM, h, ffn_scale, nullptr, nullptr, nullptr);
}